// round 1
// baseline (speedup 1.0000x reference)
#include <cuda_runtime.h>
#include <math.h>

#define BATCHN 32
#define LSEQ   196
#define DM     384
#define DI     768
#define DS     16
#define DTR    24
#define DBCN   56        // DT_RANK + 2*D_STATE
#define DEPTH  12
#define MROWS  (BATCHN*LSEQ)   // 6272

// ---------------- scratch (static device globals; no runtime alloc) ----------------
__device__ float g_x[MROWS*DM];
__device__ float g_xn[MROWS*DM];
__device__ float g_im2col[MROWS*768];
__device__ float g_wpt[768*DM];
__device__ float g_xz[2*MROWS*2*DI];   // [dir][m][1536]  (u | z)
__device__ float g_u [2*MROWS*DI];     // [dir][m][768]   post conv+silu
__device__ float g_dbc[2*MROWS*DBCN];  // [dir][m][56]
__device__ float g_dt [2*MROWS*DI];    // [dir][m][768]   post softplus
__device__ float g_y  [MROWS*2*DI];    // [m][dir*768+c]

// ---------------- generic SGEMM 128x64x16, 256 threads, 8x4 microtile ----------------
// C[M,N] = A[M,K] @ B[K,N]  (A row-major w/ row stride lda; B row-major KxN)
// EPI: 0 plain, 1 softplus(v + bias[col]), 2 C = res + v, 3 v + bias[col] + res[(m%L)*N+col]
template<int EPI>
__global__ void __launch_bounds__(256) sgemm(
    const float* __restrict__ A, const float* __restrict__ B, float* __restrict__ C,
    int M, int N, int K, int lda,
    long sA, long sB, long sC,
    const float* __restrict__ bias, long sBias,
    const float* __restrict__ res)
{
    A += (size_t)blockIdx.z * sA;
    B += (size_t)blockIdx.z * sB;
    C += (size_t)blockIdx.z * sC;
    if (bias) bias += (size_t)blockIdx.z * sBias;

    const int tid = threadIdx.x;
    const int tx = tid & 15, ty = tid >> 4;
    const int m0 = blockIdx.y * 128;
    const int n0 = blockIdx.x * 64;

    __shared__ float As[16][132];   // As[k][m], padded (row=528B, 16B aligned)
    __shared__ float Bs[16][68];    // Bs[k][n]

    float acc[8][4];
#pragma unroll
    for (int i = 0; i < 8; i++)
#pragma unroll
        for (int j = 0; j < 4; j++) acc[i][j] = 0.f;

    const int am  = tid >> 1;        // 0..127 (M within tile)
    const int akq = (tid & 1) * 8;   // k sub-offset 0 or 8
    const int bk  = tid >> 4;        // 0..15
    const int bn  = (tid & 15) * 4;  // 0..60

    for (int k0 = 0; k0 < K; k0 += 16) {
        // A tile -> As[k][m] (transposed store, 2x float4 per thread)
        {
            float4 v0 = make_float4(0.f,0.f,0.f,0.f), v1 = v0;
            if (k0 + akq < K) {  // all K here are multiples of 8
                const float* ap = A + (size_t)(m0 + am) * lda + k0 + akq;
                v0 = *(const float4*)(ap);
                v1 = *(const float4*)(ap + 4);
            }
            As[akq+0][am] = v0.x; As[akq+1][am] = v0.y;
            As[akq+2][am] = v0.z; As[akq+3][am] = v0.w;
            As[akq+4][am] = v1.x; As[akq+5][am] = v1.y;
            As[akq+6][am] = v1.z; As[akq+7][am] = v1.w;
        }
        // B tile -> Bs[k][n]
        {
            float4 v = make_float4(0.f,0.f,0.f,0.f);
            if (k0 + bk < K) {
                const float* bp = B + (size_t)(k0 + bk) * N + n0 + bn;
                if (n0 + bn + 3 < N) {
                    v = *(const float4*)bp;
                } else {
                    if (n0+bn+0 < N) v.x = bp[0];
                    if (n0+bn+1 < N) v.y = bp[1];
                    if (n0+bn+2 < N) v.z = bp[2];
                    if (n0+bn+3 < N) v.w = bp[3];
                }
            }
            *(float4*)&Bs[bk][bn] = v;
        }
        __syncthreads();
#pragma unroll
        for (int kk = 0; kk < 16; kk++) {
            float4 a0 = *(const float4*)&As[kk][ty*8];
            float4 a1 = *(const float4*)&As[kk][ty*8+4];
            float4 b4 = *(const float4*)&Bs[kk][tx*4];
            float a[8] = {a0.x,a0.y,a0.z,a0.w,a1.x,a1.y,a1.z,a1.w};
            float bb[4] = {b4.x,b4.y,b4.z,b4.w};
#pragma unroll
            for (int i = 0; i < 8; i++)
#pragma unroll
                for (int j = 0; j < 4; j++)
                    acc[i][j] = fmaf(a[i], bb[j], acc[i][j]);
        }
        __syncthreads();
    }

#pragma unroll
    for (int i = 0; i < 8; i++) {
        int r = m0 + ty*8 + i;
#pragma unroll
        for (int j = 0; j < 4; j++) {
            int col = n0 + tx*4 + j;
            if (col >= N) continue;
            float v = acc[i][j];
            size_t off = (size_t)r * N + col;
            if (EPI == 0) {
                C[off] = v;
            } else if (EPI == 1) {
                v += bias[col];
                C[off] = (v > 0.f) ? v + log1pf(__expf(-v)) : log1pf(__expf(v));
            } else if (EPI == 2) {
                C[off] = res[off] + v;
            } else {
                C[off] = v + bias[col] + res[(size_t)(r % LSEQ) * N + col];
            }
        }
    }
}

// ---------------- LayerNorm over last dim (384), one 128-thread block per row ----------------
__global__ void __launch_bounds__(128) ln_kernel(
    const float* __restrict__ x, float* __restrict__ y,
    const float* __restrict__ g, const float* __restrict__ b)
{
    const int row = blockIdx.x;
    const int tid = threadIdx.x;
    const float* xr = x + (size_t)row * DM;
    float v0 = xr[tid], v1 = xr[tid + 128], v2 = xr[tid + 256];
    __shared__ float sh[4];
    float s = v0 + v1 + v2;
#pragma unroll
    for (int o = 16; o > 0; o >>= 1) s += __shfl_xor_sync(0xffffffffu, s, o);
    if ((tid & 31) == 0) sh[tid >> 5] = s;
    __syncthreads();
    float mu = (sh[0] + sh[1] + sh[2] + sh[3]) * (1.f / DM);
    float d0 = v0 - mu, d1 = v1 - mu, d2 = v2 - mu;
    float q = d0*d0 + d1*d1 + d2*d2;
    __syncthreads();
#pragma unroll
    for (int o = 16; o > 0; o >>= 1) q += __shfl_xor_sync(0xffffffffu, q, o);
    if ((tid & 31) == 0) sh[tid >> 5] = q;
    __syncthreads();
    float var = (sh[0] + sh[1] + sh[2] + sh[3]) * (1.f / DM);
    float rs = rsqrtf(var + 1e-5f);
    float* yr = y + (size_t)row * DM;
    yr[tid]       = d0 * rs * g[tid]       + b[tid];
    yr[tid + 128] = d1 * rs * g[tid + 128] + b[tid + 128];
    yr[tid + 256] = d2 * rs * g[tid + 256] + b[tid + 256];
}

// ---------------- causal conv1d (width 4, depthwise) + SiLU ----------------
// dir 0: y[l] = b + sum_k w[k]*u[l-3+k] ; dir 1 (reversed seq): y[l] = b + sum_k w[k]*u[l+3-k]
__global__ void conv_silu(const float* __restrict__ xz, const float* __restrict__ w,
                          const float* __restrict__ bias, float* __restrict__ u)
{
    int idx = blockIdx.x * blockDim.x + threadIdx.x;
    if (idx >= 2 * MROWS * DI) return;
    int c   = idx % DI;
    int m   = (idx / DI) % MROWS;
    int dir = idx / (DI * MROWS);
    int l = m % LSEQ;
    int mbase = m - l;
    const float* xzd = xz + (size_t)dir * MROWS * 2 * DI;
    const float* wp = w + ((size_t)dir * DI + c) * 4;
    float w0 = wp[0], w1 = wp[1], w2 = wp[2], w3 = wp[3];
    float acc = bias[dir * DI + c];
#pragma unroll
    for (int k = 0; k < 4; k++) {
        int ls = dir ? (l + 3 - k) : (l - 3 + k);
        if (ls >= 0 && ls < LSEQ) {
            float wv = (k == 0) ? w0 : (k == 1) ? w1 : (k == 2) ? w2 : w3;
            acc += wv * xzd[(size_t)(mbase + ls) * 2 * DI + c];
        }
    }
    u[idx] = acc / (1.f + __expf(-acc));
}

// ---------------- selective scan + D skip + SiLU(z) gate ----------------
// one thread per (dir,b,c); B/C tiles for the whole sequence staged in SMEM
__global__ void __launch_bounds__(256) scan_kernel(
    const float* __restrict__ dt, const float* __restrict__ u,
    const float* __restrict__ dbc, const float* __restrict__ xz,
    const float* __restrict__ A_log, const float* __restrict__ Dp,
    float* __restrict__ y)
{
    const int c   = blockIdx.x * 256 + threadIdx.x;  // 0..767
    const int b   = blockIdx.y;
    const int dir = blockIdx.z;

    __shared__ float Bsh[LSEQ][DS];
    __shared__ float Csh[LSEQ][DS];
    const float* dbcb = dbc + ((size_t)dir * MROWS + (size_t)b * LSEQ) * DBCN;
    for (int i = threadIdx.x; i < LSEQ * 2 * DS; i += 256) {
        int l = i >> 5, j = i & 31;
        float v = dbcb[(size_t)l * DBCN + DTR + j];
        if (j < DS) Bsh[l][j] = v; else Csh[l][j - DS] = v;
    }
    __syncthreads();

    float a[DS];
    const float* ap = A_log + ((size_t)dir * DI + c) * DS;
#pragma unroll
    for (int n = 0; n < DS; n++) a[n] = -__expf(ap[n]);
    const float dp = Dp[dir * DI + c];

    float h[DS];
#pragma unroll
    for (int n = 0; n < DS; n++) h[n] = 0.f;

    const float* dtb = dt + ((size_t)dir * MROWS + (size_t)b * LSEQ) * DI + c;
    const float* ub  = u  + ((size_t)dir * MROWS + (size_t)b * LSEQ) * DI + c;
    const float* zb  = xz + ((size_t)dir * MROWS + (size_t)b * LSEQ) * 2 * DI + DI + c;
    float* yb = y + ((size_t)b * LSEQ) * 2 * DI + (size_t)dir * DI + c;

    for (int t = 0; t < LSEQ; t++) {
        int l = dir ? (LSEQ - 1 - t) : t;
        float dtv = dtb[(size_t)l * DI];
        float uv  = ub [(size_t)l * DI];
        float du = dtv * uv;
        float acc = 0.f;
#pragma unroll
        for (int n = 0; n < DS; n++) {
            h[n] = __expf(dtv * a[n]) * h[n] + du * Bsh[l][n];
            acc = fmaf(h[n], Csh[l][n], acc);
        }
        float yv = acc + dp * uv;
        float zv = zb[(size_t)l * 2 * DI];
        yb[(size_t)l * 2 * DI] = yv * (zv / (1.f + __expf(-zv)));
    }
}

// ---------------- final LN + mean-pool + two linear heads ----------------
__global__ void __launch_bounds__(384) final_head(
    const float* __restrict__ x, const float* __restrict__ g, const float* __restrict__ bb,
    const float* __restrict__ wdev, const float* __restrict__ bdev,
    const float* __restrict__ wdist, const float* __restrict__ bdist,
    float* __restrict__ out)
{
    const int b = blockIdx.x;
    const int tid = threadIdx.x;
    __shared__ float sh[12];
    __shared__ float pooled_s[DM];
    float pooled = 0.f;
    for (int l = 0; l < LSEQ; l++) {
        float v = x[((size_t)b * LSEQ + l) * DM + tid];
        float s = v;
#pragma unroll
        for (int o = 16; o > 0; o >>= 1) s += __shfl_xor_sync(0xffffffffu, s, o);
        if ((tid & 31) == 0) sh[tid >> 5] = s;
        __syncthreads();
        float mu = 0.f;
#pragma unroll
        for (int w = 0; w < 12; w++) mu += sh[w];
        mu *= (1.f / DM);
        float d = v - mu;
        float q = d * d;
        __syncthreads();
#pragma unroll
        for (int o = 16; o > 0; o >>= 1) q += __shfl_xor_sync(0xffffffffu, q, o);
        if ((tid & 31) == 0) sh[tid >> 5] = q;
        __syncthreads();
        float var = 0.f;
#pragma unroll
        for (int w = 0; w < 12; w++) var += sh[w];
        var *= (1.f / DM);
        float rs = rsqrtf(var + 1e-5f);
        pooled += d * rs * g[tid] + bb[tid];
        __syncthreads();
    }
    pooled_s[tid] = pooled * (1.f / LSEQ);
    __syncthreads();
    if (tid < 7) {
        float s = bdev[tid];
        for (int d = 0; d < DM; d++) s += pooled_s[d] * wdev[d * 7 + tid];
        out[b * 7 + tid] = s;
    } else if (tid < 11) {
        int j = tid - 7;
        float s = bdist[j];
        for (int d = 0; d < DM; d++) s += pooled_s[d] * wdist[d * 4 + j];
        out[BATCHN * 7 + b * 4 + j] = s;
    }
}

// ---------------- patch-embedding helpers ----------------
__global__ void im2col_kernel(const float* __restrict__ img)
{
    int idx = blockIdx.x * blockDim.x + threadIdx.x;
    if (idx >= MROWS * 768) return;
    int k = idx % 768;
    int m = idx / 768;
    int b = m / LSEQ, l = m % LSEQ;
    int ph = l / 14, pw = l % 14;
    int ch  = k >> 8;
    int r   = (k >> 4) & 15;
    int col = k & 15;
    g_im2col[idx] = img[(((size_t)b * 3 + ch) * 224 + ph * 16 + r) * 224 + pw * 16 + col];
}

__global__ void transpose_w(const float* __restrict__ w)
{
    int idx = blockIdx.x * blockDim.x + threadIdx.x;
    if (idx >= 768 * DM) return;
    int d = idx % DM, k = idx / DM;
    g_wpt[idx] = w[(size_t)d * 768 + k];
}

// ---------------- launcher ----------------
extern "C" void kernel_launch(void* const* d_in, const int* in_sizes, int n_in,
                              void* d_out, int out_size)
{
    const float* images  = (const float*)d_in[0];
    const float* patch_w = (const float*)d_in[1];
    const float* patch_b = (const float*)d_in[2];
    const float* pos_emb = (const float*)d_in[3];
    const float* ln_g    = (const float*)d_in[4];
    const float* ln_b    = (const float*)d_in[5];
    const float* in_w    = (const float*)d_in[6];
    const float* conv_w  = (const float*)d_in[7];
    const float* conv_b  = (const float*)d_in[8];
    const float* xproj_w = (const float*)d_in[9];
    const float* dt_w    = (const float*)d_in[10];
    const float* dt_b    = (const float*)d_in[11];
    const float* A_log   = (const float*)d_in[12];
    const float* Dp      = (const float*)d_in[13];
    const float* out_w   = (const float*)d_in[14];
    const float* fln_g   = (const float*)d_in[15];
    const float* fln_b   = (const float*)d_in[16];
    const float* hdev_w  = (const float*)d_in[17];
    const float* hdev_b  = (const float*)d_in[18];
    const float* hdist_w = (const float*)d_in[19];
    const float* hdist_b = (const float*)d_in[20];
    float* out = (float*)d_out;

    float *x, *xn, *im2c, *wpt, *xz, *u, *dbcv, *dtv, *yv;
    cudaGetSymbolAddress((void**)&x,    g_x);
    cudaGetSymbolAddress((void**)&xn,   g_xn);
    cudaGetSymbolAddress((void**)&im2c, g_im2col);
    cudaGetSymbolAddress((void**)&wpt,  g_wpt);
    cudaGetSymbolAddress((void**)&xz,   g_xz);
    cudaGetSymbolAddress((void**)&u,    g_u);
    cudaGetSymbolAddress((void**)&dbcv, g_dbc);
    cudaGetSymbolAddress((void**)&dtv,  g_dt);
    cudaGetSymbolAddress((void**)&yv,   g_y);

    const int MT = MROWS / 128;  // 49

    // ---- patch embedding: x = im2col(images) @ patch_w^T + patch_b + pos_emb ----
    transpose_w<<<(768 * DM + 255) / 256, 256>>>(patch_w);
    im2col_kernel<<<(MROWS * 768 + 255) / 256, 256>>>(images);
    sgemm<3><<<dim3(DM / 64, MT, 1), 256>>>(
        im2c, wpt, x, MROWS, DM, 768, 768,
        0, 0, 0, patch_b, 0, pos_emb);

    for (int layer = 0; layer < DEPTH; layer++) {
        // xn = LN(x)
        ln_kernel<<<MROWS, 128>>>(x, xn, ln_g + (size_t)layer * DM, ln_b + (size_t)layer * DM);

        // xz[dir] = xn @ in_w[layer,dir]   (M=6272, K=384, N=1536, batch=2)
        sgemm<0><<<dim3(1536 / 64, MT, 2), 256>>>(
            xn, in_w + (size_t)layer * 2 * DM * 2 * DI, xz,
            MROWS, 2 * DI, DM, DM,
            0, (long)DM * 2 * DI, (long)MROWS * 2 * DI, nullptr, 0, nullptr);

        // u = silu(causal_conv(xz[:, :768]))
        conv_silu<<<(2 * MROWS * DI + 255) / 256, 256>>>(
            xz, conv_w + (size_t)layer * 2 * DI * 4, conv_b + (size_t)layer * 2 * DI, u);

        // dbc = u @ xproj_w   (K=768, N=56, batch=2)
        sgemm<0><<<dim3(1, MT, 2), 256>>>(
            u, xproj_w + (size_t)layer * 2 * DI * DBCN, dbcv,
            MROWS, DBCN, DI, DI,
            (long)MROWS * DI, (long)DI * DBCN, (long)MROWS * DBCN, nullptr, 0, nullptr);

        // dt = softplus(dbc[:, :24] @ dt_w + dt_b)   (K=24, lda=56, N=768, batch=2)
        sgemm<1><<<dim3(DI / 64, MT, 2), 256>>>(
            dbcv, dt_w + (size_t)layer * 2 * DTR * DI, dtv,
            MROWS, DI, DTR, DBCN,
            (long)MROWS * DBCN, (long)DTR * DI, (long)MROWS * DI,
            dt_b + (size_t)layer * 2 * DI, (long)DI, nullptr);

        // selective scan + gate -> y[m][dir*768+c]
        scan_kernel<<<dim3(3, BATCHN, 2), 256>>>(
            dtv, u, dbcv, xz,
            A_log + (size_t)layer * 2 * DI * DS, Dp + (size_t)layer * 2 * DI, yv);

        // x = x + y @ out_w[layer] (dirs stacked: K=1536, N=384)
        sgemm<2><<<dim3(DM / 64, MT, 1), 256>>>(
            yv, out_w + (size_t)layer * 2 * DI * DM, x,
            MROWS, DM, 2 * DI, 2 * DI,
            0, 0, 0, nullptr, 0, x);
    }

    // final LN + pool + heads
    final_head<<<BATCHN, 384>>>(x, fln_g, fln_b, hdev_w, hdev_b, hdist_w, hdist_b, out);
    (void)in_sizes; (void)n_in; (void)out_size;
}

// round 3
// speedup vs baseline: 1.4695x; 1.4695x over previous
#include <cuda_runtime.h>
#include <math.h>
#include <stdint.h>

#define BATCHN 32
#define LSEQ   196
#define DM     384
#define DI     768
#define DS     16
#define DTR    24
#define DBCN   56
#define DEPTH  12
#define MROWS  (BATCHN*LSEQ)   // 6272

// tcgen05 only exists in the arch-specific (sm_103a) compilation pass.
#if defined(__CUDA_ARCH__) && (defined(__CUDA_ARCH_FEAT_SM103_ALL) || defined(__CUDA_ARCH_SPECIFIC__))
#define HAS_TC 1
#else
#define HAS_TC 0
#endif

// ---------------- scratch ----------------
__device__ float g_x[MROWS*DM];
__device__ float g_xn[MROWS*DM];
__device__ float g_im2col[MROWS*768];
__device__ float g_xz[2*MROWS*2*DI];
__device__ float g_u [2*MROWS*DI];
__device__ float g_dbc[2*MROWS*DBCN];
__device__ float g_dt [2*MROWS*DI];
__device__ float g_y  [MROWS*2*DI];
__device__ float g_inwT [DEPTH*2*2*DI*DM];  // [l*2+dir][1536][384]
__device__ float g_outwT[DEPTH*DM*2*DI];    // [l][384][1536]

// ---------------- PTX helpers (guarded) ----------------
#if HAS_TC
__device__ __forceinline__ uint32_t smem_u32(const void* p) {
    uint32_t a;
    asm("{ .reg .u64 t; cvta.to.shared.u64 t, %1; cvt.u32.u64 %0, t; }" : "=r"(a) : "l"(p));
    return a;
}
__device__ __forceinline__ uint32_t elect_one() {
    uint32_t p;
    asm volatile("{ .reg .pred p; elect.sync _|p, 0xFFFFFFFF; selp.b32 %0,1,0,p; }" : "=r"(p));
    return p;
}
__device__ __forceinline__ uint32_t f2tf32(float f) {
    uint32_t r; asm("cvt.rna.tf32.f32 %0, %1;" : "=r"(r) : "f"(f)); return r;
}
#define SWZ(o) ((o) ^ (((o) >> 3) & 0x70))

static __device__ __forceinline__ uint64_t make_desc(uint32_t addr) {
    // SW128, Blackwell version=1, LBO=1, SBO=64
    const uint64_t base =
        (uint64_t(2) << 61) | (uint64_t(1) << 46) | (uint64_t(64) << 32) | (uint64_t(1) << 16);
    return base | ((uint64_t)(addr >> 4) & 0x3FFF);
}

#define MBAR_INIT(a, c) \
    asm volatile("mbarrier.init.shared.b64 [%0], %1;" :: "r"(a), "r"(c) : "memory")
#define MBAR_INVAL(a) \
    asm volatile("mbarrier.inval.shared.b64 [%0];" :: "r"(a) : "memory")
#define MBAR_WAIT(a, ph) do {                                            \
    uint32_t _m = (a); uint32_t _p = (ph); uint32_t _d;                  \
    asm volatile("{ .reg .pred p; mbarrier.try_wait.parity.acquire.cta.shared::cta.b64 p,[%1],%2; selp.b32 %0,1,0,p; }" \
        : "=r"(_d) : "r"(_m), "r"(_p) : "memory");                       \
    if (!_d) {                                                           \
        asm volatile("{ .reg .pred P1; W%=: mbarrier.try_wait.parity.acquire.cta.shared::cta.b64 P1,[%0],%1,0x989680; @P1 bra.uni D%=; bra.uni W%=; D%=: }" \
            :: "r"(_m), "r"(_p) : "memory");                             \
    } } while (0)

__device__ __forceinline__ void tc_alloc(uint32_t smem_dst, uint32_t ncols) {
    asm volatile("tcgen05.alloc.cta_group::1.sync.aligned.shared::cta.b32 [%0], %1;"
                 :: "r"(smem_dst), "r"(ncols) : "memory");
}
__device__ __forceinline__ void tc_relinq() {
    asm volatile("tcgen05.relinquish_alloc_permit.cta_group::1.sync.aligned;");
}
__device__ __forceinline__ void tc_dealloc(uint32_t tmem, uint32_t ncols) {
    asm volatile("tcgen05.dealloc.cta_group::1.sync.aligned.b32 %0, %1;" :: "r"(tmem), "r"(ncols));
}
__device__ __forceinline__ void tc_commit(uint32_t mbar) {
    asm volatile("tcgen05.commit.cta_group::1.mbarrier::arrive::one.shared::cluster.b64 [%0];"
                 :: "r"(mbar) : "memory");
}
__device__ __forceinline__ void mma_tf32(uint32_t d, uint64_t ad, uint64_t bd, uint32_t idesc, bool acc) {
    uint32_t en = acc ? 1u : 0u, z = 0u;
    asm volatile(
        "{ .reg .pred p; setp.ne.u32 p, %5, 0;"
        " tcgen05.mma.cta_group::1.kind::tf32 [%0], %1, %2, %3, {%4,%4,%4,%4}, p; }"
        :: "r"(d), "l"(ad), "l"(bd), "r"(idesc), "r"(z), "r"(en) : "memory");
}
#define TC_LD_X32(r, a)                                                     \
    asm volatile("tcgen05.ld.sync.aligned.32x32b.x32.b32 "                  \
        "{%0,%1,%2,%3,%4,%5,%6,%7,%8,%9,%10,%11,%12,%13,%14,%15,"           \
        "%16,%17,%18,%19,%20,%21,%22,%23,%24,%25,%26,%27,%28,%29,%30,%31}, [%32];" \
        : "=r"((r)[0]),"=r"((r)[1]),"=r"((r)[2]),"=r"((r)[3]),"=r"((r)[4]),"=r"((r)[5]),"=r"((r)[6]),"=r"((r)[7]), \
          "=r"((r)[8]),"=r"((r)[9]),"=r"((r)[10]),"=r"((r)[11]),"=r"((r)[12]),"=r"((r)[13]),"=r"((r)[14]),"=r"((r)[15]), \
          "=r"((r)[16]),"=r"((r)[17]),"=r"((r)[18]),"=r"((r)[19]),"=r"((r)[20]),"=r"((r)[21]),"=r"((r)[22]),"=r"((r)[23]), \
          "=r"((r)[24]),"=r"((r)[25]),"=r"((r)[26]),"=r"((r)[27]),"=r"((r)[28]),"=r"((r)[29]),"=r"((r)[30]),"=r"((r)[31]) \
        : "r"(a))
#define TC_WAIT_LD() asm volatile("tcgen05.wait::ld.sync.aligned;" ::: "memory")
#define TC_FENCE_AFTER() asm volatile("tcgen05.fence::after_thread_sync;" ::: "memory")
#endif  // HAS_TC

// ---------------- GEMM: C[M,N] = A[M,K] @ BwT[N,K]^T ----------------
// tile 128 x NT, K-step 32. EPI: 0 store, 2 += res(full), 3 + bias[col] + res[(m%L)*N+col]
// sm_103a pass: tcgen05 TF32 MMA. Non-arch-specific pass: SIMT fp32 fallback (correct, slow).
template<int NT, int EPI>
__global__ void __launch_bounds__(128) mma_gemm(
    const float* __restrict__ A, int lda, long sA,
    const float* __restrict__ Bw, long sB,
    float* __restrict__ C, long sC,
    int N, int K,
    const float* __restrict__ bias,
    const float* __restrict__ res)
{
#if HAS_TC
    extern __shared__ char smem[];
    const uint32_t sb = smem_u32(smem);
    const int tid = threadIdx.x;
    const int wid = tid >> 5, lane = tid & 31;
    const int m0 = blockIdx.y * 128, n0 = blockIdx.x * NT;

    A  += (size_t)blockIdx.z * sA;
    Bw += (size_t)blockIdx.z * sB;
    C  += (size_t)blockIdx.z * sC;

    if (tid == 0) { MBAR_INIT(sb + 8, 1); MBAR_INIT(sb + 16, 1); }
    if (wid == 0) { tc_alloc(sb, NT); tc_relinq(); }
    __syncthreads();
    uint32_t tmem;
    asm volatile("ld.shared.b32 %0, [%1];" : "=r"(tmem) : "r"(sb));

    constexpr int BUFB = 16384 + NT * 128;
    const uint32_t idesc = 0x10u | (2u << 7) | (2u << 10) | ((uint32_t)(NT / 8) << 17) | (8u << 24);

    int ph0 = 0, ph1 = 0;
    const int S = K >> 5;

    for (int s = 0; s < S; s++) {
        const int b = s & 1;
        if (s >= 2) {
            if (b == 0) { MBAR_WAIT(sb + 8, ph0);  ph0 ^= 1; }
            else        { MBAR_WAIT(sb + 16, ph1); ph1 ^= 1; }
        }
        const int k0 = s << 5;
        char* abuf = smem + 1024 + b * BUFB;
        char* bbuf = abuf + 16384;
        // A tile: 128 rows x 32 floats, K-major SW128
#pragma unroll
        for (int i = 0; i < 8; i++) {
            int f = i * 128 + tid;
            int row = f >> 3, q = f & 7;
            float4 v = *(const float4*)(A + (size_t)(m0 + row) * lda + k0 + q * 4);
            uint4 w; w.x = f2tf32(v.x); w.y = f2tf32(v.y); w.z = f2tf32(v.z); w.w = f2tf32(v.w);
            *(uint4*)(abuf + SWZ(row * 128 + q * 16)) = w;
        }
        // B tile: NT rows x 32 floats
#pragma unroll
        for (int i = 0; i < NT / 16; i++) {
            int f = i * 128 + tid;
            int row = f >> 3, q = f & 7;
            float4 v = *(const float4*)(Bw + (size_t)(n0 + row) * K + k0 + q * 4);
            uint4 w; w.x = f2tf32(v.x); w.y = f2tf32(v.y); w.z = f2tf32(v.z); w.w = f2tf32(v.w);
            *(uint4*)(bbuf + SWZ(row * 128 + q * 16)) = w;
        }
        asm volatile("fence.proxy.async.shared::cta;" ::: "memory");
        __syncthreads();
        if (wid == 0 && elect_one()) {
            uint64_t ad = make_desc(sb + 1024 + b * BUFB);
            uint64_t bd = make_desc(sb + 1024 + b * BUFB + 16384);
#pragma unroll
            for (int sl = 0; sl < 4; sl++)
                mma_tf32(tmem, ad + sl * 2, bd + sl * 2, idesc, (s > 0) || (sl > 0));
            tc_commit(sb + 8 + b * 8);
        }
    }
    MBAR_WAIT(sb + 8, ph0);
    MBAR_WAIT(sb + 16, ph1);
    TC_FENCE_AFTER();

    // epilogue: warp w owns rows m0 + w*32 + lane
#pragma unroll
    for (int ch = 0; ch < NT / 32; ch++) {
        uint32_t r[32];
        TC_LD_X32(r, tmem + ch * 32);
        TC_WAIT_LD();
        const int row = m0 + wid * 32 + lane;
        const int col0 = n0 + ch * 32;
        float* cp = C + (size_t)row * N + col0;
        float vals[32];
#pragma unroll
        for (int j = 0; j < 32; j++) {
            float v = __uint_as_float(r[j]);
            if (EPI == 2) v += res[(size_t)row * N + col0 + j];
            if (EPI == 3) v += bias[col0 + j] + res[(size_t)(row % LSEQ) * N + col0 + j];
            vals[j] = v;
        }
#pragma unroll
        for (int g = 0; g < 8; g++)
            *(float4*)(cp + g * 4) = make_float4(vals[4*g], vals[4*g+1], vals[4*g+2], vals[4*g+3]);
    }
    __syncthreads();
    if (tid == 0) { MBAR_INVAL(sb + 8); MBAR_INVAL(sb + 16); }
    if (wid == 0) tc_dealloc(tmem, NT);
#else
    // SIMT fallback: one row per thread, correct on any target.
    const int tid = threadIdx.x;
    const int m0 = blockIdx.y * 128, n0 = blockIdx.x * NT;
    A  += (size_t)blockIdx.z * sA;
    Bw += (size_t)blockIdx.z * sB;
    C  += (size_t)blockIdx.z * sC;
    const int row = m0 + tid;
    const float* ar = A + (size_t)row * lda;
    for (int n = 0; n < NT; n++) {
        const float* br = Bw + (size_t)(n0 + n) * K;
        float acc = 0.f;
        for (int k = 0; k < K; k++) acc = fmaf(ar[k], br[k], acc);
        int col = n0 + n;
        float v = acc;
        if (EPI == 2) v += res[(size_t)row * N + col];
        if (EPI == 3) v += bias[col] + res[(size_t)(row % LSEQ) * N + col];
        C[(size_t)row * N + col] = v;
    }
#endif
}

// ---------------- batched transpose [z][R][C] -> [z][C][R] ----------------
__global__ void __launch_bounds__(256) transpose_k(
    const float* __restrict__ in, float* __restrict__ out, int R, int Ccol)
{
    __shared__ float t[32][33];
    const int z = blockIdx.z;
    in  += (size_t)z * R * Ccol;
    out += (size_t)z * R * Ccol;
    const int c0 = blockIdx.x * 32, r0 = blockIdx.y * 32;
    const int tx = threadIdx.x & 31, ty = threadIdx.x >> 5;  // 32 x 8
#pragma unroll
    for (int i = 0; i < 32; i += 8)
        t[ty + i][tx] = in[(size_t)(r0 + ty + i) * Ccol + c0 + tx];
    __syncthreads();
#pragma unroll
    for (int i = 0; i < 32; i += 8)
        out[(size_t)(c0 + ty + i) * R + r0 + tx] = t[tx][ty + i];
}

// ---------------- fp32 SGEMM (small GEMMs: xproj, dt) ----------------
template<int EPI>
__global__ void __launch_bounds__(256) sgemm(
    const float* __restrict__ A, const float* __restrict__ B, float* __restrict__ C,
    int M, int N, int K, int lda,
    long sA, long sB, long sC,
    const float* __restrict__ bias, long sBias)
{
    A += (size_t)blockIdx.z * sA;
    B += (size_t)blockIdx.z * sB;
    C += (size_t)blockIdx.z * sC;
    if (bias) bias += (size_t)blockIdx.z * sBias;

    const int tid = threadIdx.x;
    const int tx = tid & 15, ty = tid >> 4;
    const int m0 = blockIdx.y * 128;
    const int n0 = blockIdx.x * 64;

    __shared__ float As[16][132];
    __shared__ float Bs[16][68];

    float acc[8][4];
#pragma unroll
    for (int i = 0; i < 8; i++)
#pragma unroll
        for (int j = 0; j < 4; j++) acc[i][j] = 0.f;

    const int am  = tid >> 1;
    const int akq = (tid & 1) * 8;
    const int bk  = tid >> 4;
    const int bn  = (tid & 15) * 4;

    for (int k0 = 0; k0 < K; k0 += 16) {
        {
            float4 v0 = make_float4(0.f,0.f,0.f,0.f), v1 = v0;
            if (k0 + akq < K) {
                const float* ap = A + (size_t)(m0 + am) * lda + k0 + akq;
                v0 = *(const float4*)(ap);
                v1 = *(const float4*)(ap + 4);
            }
            As[akq+0][am] = v0.x; As[akq+1][am] = v0.y;
            As[akq+2][am] = v0.z; As[akq+3][am] = v0.w;
            As[akq+4][am] = v1.x; As[akq+5][am] = v1.y;
            As[akq+6][am] = v1.z; As[akq+7][am] = v1.w;
        }
        {
            float4 v = make_float4(0.f,0.f,0.f,0.f);
            if (k0 + bk < K) {
                const float* bp = B + (size_t)(k0 + bk) * N + n0 + bn;
                if (n0 + bn + 3 < N) v = *(const float4*)bp;
                else {
                    if (n0+bn+0 < N) v.x = bp[0];
                    if (n0+bn+1 < N) v.y = bp[1];
                    if (n0+bn+2 < N) v.z = bp[2];
                    if (n0+bn+3 < N) v.w = bp[3];
                }
            }
            *(float4*)&Bs[bk][bn] = v;
        }
        __syncthreads();
#pragma unroll
        for (int kk = 0; kk < 16; kk++) {
            float4 a0 = *(const float4*)&As[kk][ty*8];
            float4 a1 = *(const float4*)&As[kk][ty*8+4];
            float4 b4 = *(const float4*)&Bs[kk][tx*4];
            float a[8] = {a0.x,a0.y,a0.z,a0.w,a1.x,a1.y,a1.z,a1.w};
            float bb[4] = {b4.x,b4.y,b4.z,b4.w};
#pragma unroll
            for (int i = 0; i < 8; i++)
#pragma unroll
                for (int j = 0; j < 4; j++)
                    acc[i][j] = fmaf(a[i], bb[j], acc[i][j]);
        }
        __syncthreads();
    }
#pragma unroll
    for (int i = 0; i < 8; i++) {
        int r = m0 + ty*8 + i;
#pragma unroll
        for (int j = 0; j < 4; j++) {
            int col = n0 + tx*4 + j;
            if (col >= N) continue;
            float v = acc[i][j];
            size_t off = (size_t)r * N + col;
            if (EPI == 0) C[off] = v;
            else {
                v += bias[col];
                C[off] = (v > 0.f) ? v + log1pf(__expf(-v)) : log1pf(__expf(v));
            }
        }
    }
}

// ---------------- LayerNorm ----------------
__global__ void __launch_bounds__(128) ln_kernel(
    const float* __restrict__ x, float* __restrict__ y,
    const float* __restrict__ g, const float* __restrict__ b)
{
    const int row = blockIdx.x;
    const int tid = threadIdx.x;
    const float* xr = x + (size_t)row * DM;
    float v0 = xr[tid], v1 = xr[tid + 128], v2 = xr[tid + 256];
    __shared__ float sh[4];
    float s = v0 + v1 + v2;
#pragma unroll
    for (int o = 16; o > 0; o >>= 1) s += __shfl_xor_sync(0xffffffffu, s, o);
    if ((tid & 31) == 0) sh[tid >> 5] = s;
    __syncthreads();
    float mu = (sh[0] + sh[1] + sh[2] + sh[3]) * (1.f / DM);
    float d0 = v0 - mu, d1 = v1 - mu, d2 = v2 - mu;
    float q = d0*d0 + d1*d1 + d2*d2;
    __syncthreads();
#pragma unroll
    for (int o = 16; o > 0; o >>= 1) q += __shfl_xor_sync(0xffffffffu, q, o);
    if ((tid & 31) == 0) sh[tid >> 5] = q;
    __syncthreads();
    float var = (sh[0] + sh[1] + sh[2] + sh[3]) * (1.f / DM);
    float rs = rsqrtf(var + 1e-5f);
    float* yr = y + (size_t)row * DM;
    yr[tid]       = d0 * rs * g[tid]       + b[tid];
    yr[tid + 128] = d1 * rs * g[tid + 128] + b[tid + 128];
    yr[tid + 256] = d2 * rs * g[tid + 256] + b[tid + 256];
}

// ---------------- conv1d + SiLU ----------------
__global__ void conv_silu(const float* __restrict__ xz, const float* __restrict__ w,
                          const float* __restrict__ bias, float* __restrict__ u)
{
    int idx = blockIdx.x * blockDim.x + threadIdx.x;
    if (idx >= 2 * MROWS * DI) return;
    int c   = idx % DI;
    int m   = (idx / DI) % MROWS;
    int dir = idx / (DI * MROWS);
    int l = m % LSEQ;
    int mbase = m - l;
    const float* xzd = xz + (size_t)dir * MROWS * 2 * DI;
    const float* wp = w + ((size_t)dir * DI + c) * 4;
    float w0 = wp[0], w1 = wp[1], w2 = wp[2], w3 = wp[3];
    float acc = bias[dir * DI + c];
#pragma unroll
    for (int k = 0; k < 4; k++) {
        int ls = dir ? (l + 3 - k) : (l - 3 + k);
        if (ls >= 0 && ls < LSEQ) {
            float wv = (k == 0) ? w0 : (k == 1) ? w1 : (k == 2) ? w2 : w3;
            acc += wv * xzd[(size_t)(mbase + ls) * 2 * DI + c];
        }
    }
    u[idx] = acc / (1.f + __expf(-acc));
}

// ---------------- selective scan ----------------
__global__ void __launch_bounds__(256) scan_kernel(
    const float* __restrict__ dt, const float* __restrict__ u,
    const float* __restrict__ dbc, const float* __restrict__ xz,
    const float* __restrict__ A_log, const float* __restrict__ Dp,
    float* __restrict__ y)
{
    const int c   = blockIdx.x * 256 + threadIdx.x;
    const int b   = blockIdx.y;
    const int dir = blockIdx.z;

    __shared__ float Bsh[LSEQ][DS];
    __shared__ float Csh[LSEQ][DS];
    const float* dbcb = dbc + ((size_t)dir * MROWS + (size_t)b * LSEQ) * DBCN;
    for (int i = threadIdx.x; i < LSEQ * 2 * DS; i += 256) {
        int l = i >> 5, j = i & 31;
        float v = dbcb[(size_t)l * DBCN + DTR + j];
        if (j < DS) Bsh[l][j] = v; else Csh[l][j - DS] = v;
    }
    __syncthreads();

    float a[DS];
    const float* ap = A_log + ((size_t)dir * DI + c) * DS;
#pragma unroll
    for (int n = 0; n < DS; n++) a[n] = -__expf(ap[n]);
    const float dp = Dp[dir * DI + c];

    float h[DS];
#pragma unroll
    for (int n = 0; n < DS; n++) h[n] = 0.f;

    const float* dtb = dt + ((size_t)dir * MROWS + (size_t)b * LSEQ) * DI + c;
    const float* ub  = u  + ((size_t)dir * MROWS + (size_t)b * LSEQ) * DI + c;
    const float* zb  = xz + ((size_t)dir * MROWS + (size_t)b * LSEQ) * 2 * DI + DI + c;
    float* yb = y + ((size_t)b * LSEQ) * 2 * DI + (size_t)dir * DI + c;

    for (int t = 0; t < LSEQ; t++) {
        int l = dir ? (LSEQ - 1 - t) : t;
        float dtv = dtb[(size_t)l * DI];
        float uv  = ub [(size_t)l * DI];
        float du = dtv * uv;
        float acc = 0.f;
#pragma unroll
        for (int n = 0; n < DS; n++) {
            h[n] = __expf(dtv * a[n]) * h[n] + du * Bsh[l][n];
            acc = fmaf(h[n], Csh[l][n], acc);
        }
        float yv = acc + dp * uv;
        float zv = zb[(size_t)l * 2 * DI];
        yb[(size_t)l * 2 * DI] = yv * (zv / (1.f + __expf(-zv)));
    }
}

// ---------------- final LN + pool + heads ----------------
__global__ void __launch_bounds__(384) final_head(
    const float* __restrict__ x, const float* __restrict__ g, const float* __restrict__ bb,
    const float* __restrict__ wdev, const float* __restrict__ bdev,
    const float* __restrict__ wdist, const float* __restrict__ bdist,
    float* __restrict__ out)
{
    const int b = blockIdx.x;
    const int tid = threadIdx.x;
    __shared__ float sh[12];
    __shared__ float pooled_s[DM];
    float pooled = 0.f;
    for (int l = 0; l < LSEQ; l++) {
        float v = x[((size_t)b * LSEQ + l) * DM + tid];
        float s = v;
#pragma unroll
        for (int o = 16; o > 0; o >>= 1) s += __shfl_xor_sync(0xffffffffu, s, o);
        if ((tid & 31) == 0) sh[tid >> 5] = s;
        __syncthreads();
        float mu = 0.f;
#pragma unroll
        for (int w = 0; w < 12; w++) mu += sh[w];
        mu *= (1.f / DM);
        float d = v - mu;
        float q = d * d;
        __syncthreads();
#pragma unroll
        for (int o = 16; o > 0; o >>= 1) q += __shfl_xor_sync(0xffffffffu, q, o);
        if ((tid & 31) == 0) sh[tid >> 5] = q;
        __syncthreads();
        float var = 0.f;
#pragma unroll
        for (int w = 0; w < 12; w++) var += sh[w];
        var *= (1.f / DM);
        float rs = rsqrtf(var + 1e-5f);
        pooled += d * rs * g[tid] + bb[tid];
        __syncthreads();
    }
    pooled_s[tid] = pooled * (1.f / LSEQ);
    __syncthreads();
    if (tid < 7) {
        float s = bdev[tid];
        for (int d = 0; d < DM; d++) s += pooled_s[d] * wdev[d * 7 + tid];
        out[b * 7 + tid] = s;
    } else if (tid < 11) {
        int j = tid - 7;
        float s = bdist[j];
        for (int d = 0; d < DM; d++) s += pooled_s[d] * wdist[d * 4 + j];
        out[BATCHN * 7 + b * 4 + j] = s;
    }
}

// ---------------- im2col ----------------
__global__ void im2col_kernel(const float* __restrict__ img)
{
    int idx = blockIdx.x * blockDim.x + threadIdx.x;
    if (idx >= MROWS * 768) return;
    int k = idx % 768;
    int m = idx / 768;
    int b = m / LSEQ, l = m % LSEQ;
    int ph = l / 14, pw = l % 14;
    int ch  = k >> 8;
    int r   = (k >> 4) & 15;
    int col = k & 15;
    g_im2col[idx] = img[(((size_t)b * 3 + ch) * 224 + ph * 16 + r) * 224 + pw * 16 + col];
}

// ---------------- launcher ----------------
extern "C" void kernel_launch(void* const* d_in, const int* in_sizes, int n_in,
                              void* d_out, int out_size)
{
    const float* images  = (const float*)d_in[0];
    const float* patch_w = (const float*)d_in[1];
    const float* patch_b = (const float*)d_in[2];
    const float* pos_emb = (const float*)d_in[3];
    const float* ln_g    = (const float*)d_in[4];
    const float* ln_b    = (const float*)d_in[5];
    const float* in_w    = (const float*)d_in[6];
    const float* conv_w  = (const float*)d_in[7];
    const float* conv_b  = (const float*)d_in[8];
    const float* xproj_w = (const float*)d_in[9];
    const float* dt_w    = (const float*)d_in[10];
    const float* dt_b    = (const float*)d_in[11];
    const float* A_log   = (const float*)d_in[12];
    const float* Dp      = (const float*)d_in[13];
    const float* out_w   = (const float*)d_in[14];
    const float* fln_g   = (const float*)d_in[15];
    const float* fln_b   = (const float*)d_in[16];
    const float* hdev_w  = (const float*)d_in[17];
    const float* hdev_b  = (const float*)d_in[18];
    const float* hdist_w = (const float*)d_in[19];
    const float* hdist_b = (const float*)d_in[20];
    float* out = (float*)d_out;

    float *x, *xn, *im2c, *xz, *u, *dbcv, *dtv, *yv, *inwT, *outwT;
    cudaGetSymbolAddress((void**)&x,     g_x);
    cudaGetSymbolAddress((void**)&xn,    g_xn);
    cudaGetSymbolAddress((void**)&im2c,  g_im2col);
    cudaGetSymbolAddress((void**)&xz,    g_xz);
    cudaGetSymbolAddress((void**)&u,     g_u);
    cudaGetSymbolAddress((void**)&dbcv,  g_dbc);
    cudaGetSymbolAddress((void**)&dtv,   g_dt);
    cudaGetSymbolAddress((void**)&yv,    g_y);
    cudaGetSymbolAddress((void**)&inwT,  g_inwT);
    cudaGetSymbolAddress((void**)&outwT, g_outwT);

    const int SMEM_N128 = 1024 + 2 * (16384 + 128 * 128);
    const int SMEM_N64  = 1024 + 2 * (16384 + 64 * 128);
    cudaFuncSetAttribute(mma_gemm<128,0>, cudaFuncAttributeMaxDynamicSharedMemorySize, SMEM_N128);
    cudaFuncSetAttribute(mma_gemm<64,2>,  cudaFuncAttributeMaxDynamicSharedMemorySize, SMEM_N64);
    cudaFuncSetAttribute(mma_gemm<64,3>,  cudaFuncAttributeMaxDynamicSharedMemorySize, SMEM_N64);

    const int MT = MROWS / 128;  // 49

    // weight transposes: in_w [24][384][1536] -> [24][1536][384]; out_w [12][1536][384] -> [12][384][1536]
    transpose_k<<<dim3(1536/32, 384/32, 24), 256>>>(in_w, inwT, 384, 1536);
    transpose_k<<<dim3(384/32, 1536/32, 12), 256>>>(out_w, outwT, 1536, 384);

    // patch embedding: x = im2col @ patch_w^T + patch_b + pos_emb  (patch_w already [384][768])
    im2col_kernel<<<(MROWS * 768 + 255) / 256, 256>>>(images);
    mma_gemm<64,3><<<dim3(DM/64, MT, 1), 128, SMEM_N64>>>(
        im2c, 768, 0, patch_w, 0, x, 0, DM, 768, patch_b, pos_emb);

    for (int layer = 0; layer < DEPTH; layer++) {
        ln_kernel<<<MROWS, 128>>>(x, xn, ln_g + (size_t)layer * DM, ln_b + (size_t)layer * DM);

        // xz[dir] = xn @ in_w[layer,dir]  via tf32 MMA
        mma_gemm<128,0><<<dim3(2*DI/128, MT, 2), 128, SMEM_N128>>>(
            xn, DM, 0,
            inwT + (size_t)layer * 2 * 2 * DI * DM, (long)2 * DI * DM,
            xz, (long)MROWS * 2 * DI,
            2 * DI, DM, nullptr, nullptr);

        conv_silu<<<(2 * MROWS * DI + 255) / 256, 256>>>(
            xz, conv_w + (size_t)layer * 2 * DI * 4, conv_b + (size_t)layer * 2 * DI, u);

        sgemm<0><<<dim3(1, MT, 2), 256>>>(
            u, xproj_w + (size_t)layer * 2 * DI * DBCN, dbcv,
            MROWS, DBCN, DI, DI,
            (long)MROWS * DI, (long)DI * DBCN, (long)MROWS * DBCN, nullptr, 0);

        sgemm<1><<<dim3(DI / 64, MT, 2), 256>>>(
            dbcv, dt_w + (size_t)layer * 2 * DTR * DI, dtv,
            MROWS, DI, DTR, DBCN,
            (long)MROWS * DBCN, (long)DTR * DI, (long)MROWS * DI,
            dt_b + (size_t)layer * 2 * DI, (long)DI);

        scan_kernel<<<dim3(3, BATCHN, 2), 256>>>(
            dtv, u, dbcv, xz,
            A_log + (size_t)layer * 2 * DI * DS, Dp + (size_t)layer * 2 * DI, yv);

        // x += y @ out_w[layer]  via tf32 MMA (dirs stacked, K=1536)
        mma_gemm<64,2><<<dim3(DM/64, MT, 1), 128, SMEM_N64>>>(
            yv, 2 * DI, 0,
            outwT + (size_t)layer * DM * 2 * DI, 0,
            x, 0,
            DM, 2 * DI, nullptr, x);
    }

    final_head<<<BATCHN, 384>>>(x, fln_g, fln_b, hdev_w, hdev_b, hdist_w, hdist_b, out);
    (void)in_sizes; (void)n_in; (void)out_size;
}

// round 5
// speedup vs baseline: 1.9518x; 1.3282x over previous
#include <cuda_runtime.h>
#include <math.h>
#include <stdint.h>

#define BATCHN 32
#define LSEQ   196
#define DM     384
#define DI     768
#define DS     16
#define DTR    24
#define DBCN   56
#define DEPTH  12
#define MROWS  (BATCHN*LSEQ)   // 6272

// tcgen05 only exists in the arch-specific (sm_103a) compilation pass.
#if defined(__CUDA_ARCH__) && (defined(__CUDA_ARCH_FEAT_SM103_ALL) || defined(__CUDA_ARCH_SPECIFIC__))
#define HAS_TC 1
#else
#define HAS_TC 0
#endif

// ---------------- scratch ----------------
__device__ __align__(256) float g_x[MROWS*DM];
__device__ __align__(256) float g_xn[MROWS*DM];
__device__ __align__(256) float g_im2col[MROWS*768];
__device__ __align__(256) float g_xz[2*MROWS*2*DI];
__device__ __align__(256) float g_u [2*MROWS*DI];
__device__ __align__(256) float g_dbc[2*MROWS*DBCN];
__device__ __align__(256) float g_dt [2*MROWS*DI];
__device__ __align__(256) float g_y  [MROWS*2*DI];
__device__ __align__(256) float g_inwT [DEPTH*2*2*DI*DM];    // [l*2+dir][1536][384] tf32-rounded
__device__ __align__(256) float g_outwT[DEPTH*DM*2*DI];      // [l][384][1536]      tf32-rounded
__device__ __align__(256) float g_pw[DM*768];                // rounded patch_w

// ---------------- tf32 rounding (identity on non-TC pass) ----------------
__device__ __forceinline__ uint32_t f2tf32(float f) {
#if HAS_TC
    uint32_t r; asm("cvt.rna.tf32.f32 %0, %1;" : "=r"(r) : "f"(f)); return r;
#else
    return __float_as_uint(f);
#endif
}
__device__ __forceinline__ float rnd32(float f) { return __uint_as_float(f2tf32(f)); }

#if HAS_TC
__device__ __forceinline__ uint32_t smem_u32(const void* p) {
    uint32_t a;
    asm("{ .reg .u64 t; cvta.to.shared.u64 t, %1; cvt.u32.u64 %0, t; }" : "=r"(a) : "l"(p));
    return a;
}
__device__ __forceinline__ uint32_t elect_one() {
    uint32_t p;
    asm volatile("{ .reg .pred p; elect.sync _|p, 0xFFFFFFFF; selp.b32 %0,1,0,p; }" : "=r"(p));
    return p;
}
#define SWZ(o) ((o) ^ (((o) >> 3) & 0x70))

static __device__ __forceinline__ uint64_t make_desc(uint32_t addr) {
    const uint64_t base =
        (uint64_t(2) << 61) | (uint64_t(1) << 46) | (uint64_t(64) << 32) | (uint64_t(1) << 16);
    return base | ((uint64_t)(addr >> 4) & 0x3FFF);
}

#define MBAR_INIT(a, c) \
    asm volatile("mbarrier.init.shared.b64 [%0], %1;" :: "r"(a), "r"(c) : "memory")
#define MBAR_INVAL(a) \
    asm volatile("mbarrier.inval.shared.b64 [%0];" :: "r"(a) : "memory")
#define MBAR_WAIT(a, ph) do {                                            \
    uint32_t _m = (a); uint32_t _p = (ph); uint32_t _d;                  \
    asm volatile("{ .reg .pred p; mbarrier.try_wait.parity.acquire.cta.shared::cta.b64 p,[%1],%2; selp.b32 %0,1,0,p; }" \
        : "=r"(_d) : "r"(_m), "r"(_p) : "memory");                       \
    if (!_d) {                                                           \
        asm volatile("{ .reg .pred P1; W%=: mbarrier.try_wait.parity.acquire.cta.shared::cta.b64 P1,[%0],%1,0x989680; @P1 bra.uni D%=; bra.uni W%=; D%=: }" \
            :: "r"(_m), "r"(_p) : "memory");                             \
    } } while (0)

#define CP_ASYNC16(dst, src) \
    asm volatile("cp.async.cg.shared.global [%0], [%1], 16;" :: "r"(dst), "l"(src) : "memory")
#define CP_COMMIT() asm volatile("cp.async.commit_group;" ::: "memory")
// Step s's tile lives in group s+2 of the (s+4) committed before iteration s:
// wait_group 2 guarantees it; wait_group 3 does NOT (R4 race).
#define CP_WAIT2()  asm volatile("cp.async.wait_group 2;" ::: "memory")

__device__ __forceinline__ void tc_alloc(uint32_t smem_dst, uint32_t ncols) {
    asm volatile("tcgen05.alloc.cta_group::1.sync.aligned.shared::cta.b32 [%0], %1;"
                 :: "r"(smem_dst), "r"(ncols) : "memory");
}
__device__ __forceinline__ void tc_relinq() {
    asm volatile("tcgen05.relinquish_alloc_permit.cta_group::1.sync.aligned;");
}
__device__ __forceinline__ void tc_dealloc(uint32_t tmem, uint32_t ncols) {
    asm volatile("tcgen05.dealloc.cta_group::1.sync.aligned.b32 %0, %1;" :: "r"(tmem), "r"(ncols));
}
__device__ __forceinline__ void tc_commit(uint32_t mbar) {
    asm volatile("tcgen05.commit.cta_group::1.mbarrier::arrive::one.shared::cluster.b64 [%0];"
                 :: "r"(mbar) : "memory");
}
__device__ __forceinline__ void mma_tf32(uint32_t d, uint64_t ad, uint64_t bd, uint32_t idesc, bool acc) {
    uint32_t en = acc ? 1u : 0u, z = 0u;
    asm volatile(
        "{ .reg .pred p; setp.ne.u32 p, %5, 0;"
        " tcgen05.mma.cta_group::1.kind::tf32 [%0], %1, %2, %3, {%4,%4,%4,%4}, p; }"
        :: "r"(d), "l"(ad), "l"(bd), "r"(idesc), "r"(z), "r"(en) : "memory");
}
#define TC_LD_X32(r, a)                                                     \
    asm volatile("tcgen05.ld.sync.aligned.32x32b.x32.b32 "                  \
        "{%0,%1,%2,%3,%4,%5,%6,%7,%8,%9,%10,%11,%12,%13,%14,%15,"           \
        "%16,%17,%18,%19,%20,%21,%22,%23,%24,%25,%26,%27,%28,%29,%30,%31}, [%32];" \
        : "=r"((r)[0]),"=r"((r)[1]),"=r"((r)[2]),"=r"((r)[3]),"=r"((r)[4]),"=r"((r)[5]),"=r"((r)[6]),"=r"((r)[7]), \
          "=r"((r)[8]),"=r"((r)[9]),"=r"((r)[10]),"=r"((r)[11]),"=r"((r)[12]),"=r"((r)[13]),"=r"((r)[14]),"=r"((r)[15]), \
          "=r"((r)[16]),"=r"((r)[17]),"=r"((r)[18]),"=r"((r)[19]),"=r"((r)[20]),"=r"((r)[21]),"=r"((r)[22]),"=r"((r)[23]), \
          "=r"((r)[24]),"=r"((r)[25]),"=r"((r)[26]),"=r"((r)[27]),"=r"((r)[28]),"=r"((r)[29]),"=r"((r)[30]),"=r"((r)[31]) \
        : "r"(a))
#define TC_WAIT_LD() asm volatile("tcgen05.wait::ld.sync.aligned;" ::: "memory")
#define TC_FENCE_AFTER() asm volatile("tcgen05.fence::after_thread_sync;" ::: "memory")
#endif  // HAS_TC

// =====================================================================
// tcgen05 TF32 GEMM, 4-stage cp.async pipeline, 256 threads.
// C[M,N] = A[M,K] @ Bw[N,K]^T  (A, Bw pre-rounded to tf32-in-fp32; lds dims mult of 32)
// EPI: 0 plain, 2 v+res, 3 v+bias[col]+res[(m%L)*ldc+col]
// =====================================================================
template<int NT, int EPI>
__global__ void __launch_bounds__(256, 1) mma_gemm(
    const float* __restrict__ A, int lda, long sA,
    const float* __restrict__ Bw, int ldb, long sB,
    float* __restrict__ C, int ldc, long sC,
    int S,
    const float* __restrict__ bias,
    const float* __restrict__ res)
{
    const int tid = threadIdx.x;
    const int m0 = blockIdx.y * 128, n0 = blockIdx.x * NT;
    A  += (size_t)blockIdx.z * sA;
    Bw += (size_t)blockIdx.z * sB;
    C  += (size_t)blockIdx.z * sC;

#if HAS_TC
    extern __shared__ char smem[];
    const uint32_t sb = smem_u32(smem);
    const int wid = tid >> 5, lane = tid & 31;
    constexpr int STAGE = 16384 + NT * 128;

    if (tid == 0) {
#pragma unroll
        for (int i = 0; i < 4; i++) MBAR_INIT(sb + 8 + i * 8, 1);
    }
    if (wid == 0) { tc_alloc(sb, NT); tc_relinq(); }
    __syncthreads();
    uint32_t tmem;
    asm volatile("ld.shared.b32 %0, [%1];" : "=r"(tmem) : "r"(sb));

    const uint32_t idesc = 0x10u | (2u << 7) | (2u << 10) | ((uint32_t)(NT / 8) << 17) | (8u << 24);

    auto stage_load = [&](int r, int step) {
        const int k0 = step << 5;
        const uint32_t ab = sb + 1024 + r * STAGE;
        const uint32_t bb = ab + 16384;
#pragma unroll
        for (int i = 0; i < 4; i++) {
            int c = i * 256 + tid; int row = c >> 3, q = c & 7;
            CP_ASYNC16(ab + SWZ(row * 128 + q * 16),
                       A + (size_t)(m0 + row) * lda + k0 + q * 4);
        }
#pragma unroll
        for (int i = 0; i < NT / 32; i++) {
            int c = i * 256 + tid; int row = c >> 3, q = c & 7;
            CP_ASYNC16(bb + SWZ(row * 128 + q * 16),
                       Bw + (size_t)(n0 + row) * ldb + k0 + q * 4);
        }
    };

    // prologue: stages 0..3 <- steps 0..3
#pragma unroll
    for (int p = 0; p < 4; p++) { stage_load(p, p); CP_COMMIT(); }

    int ph[4] = {0, 0, 0, 0};
    const int NBLK = S >> 2;
    for (int blk = 0; blk < NBLK; blk++) {
#pragma unroll
        for (int j = 0; j < 4; j++) {
            const int s = blk * 4 + j;
            CP_WAIT2();
            asm volatile("fence.proxy.async.shared::cta;" ::: "memory");
            __syncthreads();
            if (wid == 0 && elect_one()) {
                uint64_t ad = make_desc(sb + 1024 + j * STAGE);
                uint64_t bd = make_desc(sb + 1024 + j * STAGE + 16384);
#pragma unroll
                for (int sl = 0; sl < 4; sl++)
                    mma_tf32(tmem, ad + sl * 2, bd + sl * 2, idesc, (s > 0) || (sl > 0));
                tc_commit(sb + 8 + j * 8);
            }
            // lagged refill: load step s+3 into stage (j+3)&3 after MMA(s-1) done
            const int rp = (j + 3) & 3;
            if (s >= 1 && s + 3 < S) {
                MBAR_WAIT(sb + 8 + rp * 8, ph[rp]); ph[rp] ^= 1;
                stage_load(rp, s + 3);
            }
            CP_COMMIT();
        }
    }
    MBAR_WAIT(sb + 8 + 3 * 8, ph[3]);
    TC_FENCE_AFTER();

    // epilogue: warp w -> subpartition w&3 (rows), half w>>2 (cols)
    const int subp = wid & 3, half = wid >> 2;
#pragma unroll
    for (int ch = 0; ch < NT / 64; ch++) {
        const int chunk = half * (NT / 64) + ch;
        uint32_t r[32];
        TC_LD_X32(r, tmem + chunk * 32);
        TC_WAIT_LD();
        const int row = m0 + subp * 32 + lane;
        const int col0 = n0 + chunk * 32;
        float* cp = C + (size_t)row * ldc + col0;
        float vals[32];
#pragma unroll
        for (int j2 = 0; j2 < 32; j2++) {
            float v = __uint_as_float(r[j2]);
            const int col = col0 + j2;
            if (EPI == 2) v += res[(size_t)row * ldc + col];
            if (EPI == 3) v += bias[col] + res[(size_t)(row % LSEQ) * ldc + col];
            vals[j2] = v;
        }
#pragma unroll
        for (int g = 0; g < 8; g++)
            *(float4*)(cp + g * 4) =
                make_float4(vals[4*g], vals[4*g+1], vals[4*g+2], vals[4*g+3]);
    }
    __syncthreads();
    if (tid == 0) {
#pragma unroll
        for (int i = 0; i < 4; i++) MBAR_INVAL(sb + 8 + i * 8);
    }
    if (wid == 0) tc_dealloc(tmem, NT);
#else
    // SIMT fallback (non-arch-specific pass; never runs on GB300)
    if (tid >= 128) return;
    const int row = m0 + tid;
    const int K = S * 32;
    for (int n = 0; n < NT; n++) {
        const int col = n0 + n;
        const float* ar = A + (size_t)row * lda;
        const float* br = Bw + (size_t)col * ldb;
        float acc = 0.f;
        for (int k = 0; k < K; k++) acc = fmaf(ar[k], br[k], acc);
        float v = acc;
        if (EPI == 2) v += res[(size_t)row * ldc + col];
        if (EPI == 3) v += bias[col] + res[(size_t)(row % LSEQ) * ldc + col];
        C[(size_t)row * ldc + col] = v;
    }
#endif
}

// ---------------- transpose+round: out[z][i][j] = rnd(in[z][j][i]) ----------------
__global__ void __launch_bounds__(256) transpose_rnd(
    const float* __restrict__ in, float* __restrict__ out, int R, int C)
{
    __shared__ float t[32][33];
    const int z = blockIdx.z;
    in  += (size_t)z * R * C;
    out += (size_t)z * R * C;
    const int j0 = blockIdx.x * 32;  // input row base
    const int i0 = blockIdx.y * 32;  // input col base
    const int tx = threadIdx.x & 31, ty = threadIdx.x >> 5;
#pragma unroll
    for (int k = 0; k < 4; k++)
        t[ty + k * 8][tx] = rnd32(in[(size_t)(j0 + ty + k * 8) * C + i0 + tx]);
    __syncthreads();
#pragma unroll
    for (int k = 0; k < 4; k++)
        out[(size_t)(i0 + ty + k * 8) * R + j0 + tx] = t[tx][ty + k * 8];
}

// ---------------- round-copy (patch_w) ----------------
__global__ void round_copy(const float* __restrict__ in, float* __restrict__ out, int n)
{
    int i = blockIdx.x * blockDim.x + threadIdx.x;
    if (i < n) out[i] = rnd32(in[i]);
}

// ---------------- fp32 SGEMM (small GEMMs: xproj, dt) ----------------
template<int EPI>
__global__ void __launch_bounds__(256) sgemm(
    const float* __restrict__ A, const float* __restrict__ B, float* __restrict__ C,
    int M, int N, int K, int lda,
    long sA, long sB, long sC,
    const float* __restrict__ bias, long sBias)
{
    A += (size_t)blockIdx.z * sA;
    B += (size_t)blockIdx.z * sB;
    C += (size_t)blockIdx.z * sC;
    if (bias) bias += (size_t)blockIdx.z * sBias;

    const int tid = threadIdx.x;
    const int tx = tid & 15, ty = tid >> 4;
    const int m0 = blockIdx.y * 128;
    const int n0 = blockIdx.x * 64;

    __shared__ float As[16][132];
    __shared__ float Bs[16][68];

    float acc[8][4];
#pragma unroll
    for (int i = 0; i < 8; i++)
#pragma unroll
        for (int j = 0; j < 4; j++) acc[i][j] = 0.f;

    const int am  = tid >> 1;
    const int akq = (tid & 1) * 8;
    const int bk  = tid >> 4;
    const int bn  = (tid & 15) * 4;

    for (int k0 = 0; k0 < K; k0 += 16) {
        {
            float4 v0 = make_float4(0.f,0.f,0.f,0.f), v1 = v0;
            if (k0 + akq < K) {
                const float* ap = A + (size_t)(m0 + am) * lda + k0 + akq;
                v0 = *(const float4*)(ap);
                v1 = *(const float4*)(ap + 4);
            }
            As[akq+0][am] = v0.x; As[akq+1][am] = v0.y;
            As[akq+2][am] = v0.z; As[akq+3][am] = v0.w;
            As[akq+4][am] = v1.x; As[akq+5][am] = v1.y;
            As[akq+6][am] = v1.z; As[akq+7][am] = v1.w;
        }
        {
            float4 v = make_float4(0.f,0.f,0.f,0.f);
            if (k0 + bk < K) {
                const float* bp = B + (size_t)(k0 + bk) * N + n0 + bn;
                if (n0 + bn + 3 < N) v = *(const float4*)bp;
                else {
                    if (n0+bn+0 < N) v.x = bp[0];
                    if (n0+bn+1 < N) v.y = bp[1];
                    if (n0+bn+2 < N) v.z = bp[2];
                    if (n0+bn+3 < N) v.w = bp[3];
                }
            }
            *(float4*)&Bs[bk][bn] = v;
        }
        __syncthreads();
#pragma unroll
        for (int kk = 0; kk < 16; kk++) {
            float4 a0 = *(const float4*)&As[kk][ty*8];
            float4 a1 = *(const float4*)&As[kk][ty*8+4];
            float4 b4 = *(const float4*)&Bs[kk][tx*4];
            float a[8] = {a0.x,a0.y,a0.z,a0.w,a1.x,a1.y,a1.z,a1.w};
            float bb[4] = {b4.x,b4.y,b4.z,b4.w};
#pragma unroll
            for (int i = 0; i < 8; i++)
#pragma unroll
                for (int j = 0; j < 4; j++)
                    acc[i][j] = fmaf(a[i], bb[j], acc[i][j]);
        }
        __syncthreads();
    }
#pragma unroll
    for (int i = 0; i < 8; i++) {
        int r = m0 + ty*8 + i;
#pragma unroll
        for (int j = 0; j < 4; j++) {
            int col = n0 + tx*4 + j;
            if (col >= N) continue;
            float v = acc[i][j];
            size_t off = (size_t)r * N + col;
            if (EPI == 0) C[off] = v;
            else {
                v += bias[col];
                C[off] = (v > 0.f) ? v + log1pf(__expf(-v)) : log1pf(__expf(v));
            }
        }
    }
}

// ---------------- LayerNorm (rounded output; only GEMM consumes xn) ----------------
__global__ void __launch_bounds__(128) ln_kernel(
    const float* __restrict__ x, float* __restrict__ y,
    const float* __restrict__ g, const float* __restrict__ b)
{
    const int row = blockIdx.x;
    const int tid = threadIdx.x;
    const float* xr = x + (size_t)row * DM;
    float v0 = xr[tid], v1 = xr[tid + 128], v2 = xr[tid + 256];
    __shared__ float sh[4];
    float s = v0 + v1 + v2;
#pragma unroll
    for (int o = 16; o > 0; o >>= 1) s += __shfl_xor_sync(0xffffffffu, s, o);
    if ((tid & 31) == 0) sh[tid >> 5] = s;
    __syncthreads();
    float mu = (sh[0] + sh[1] + sh[2] + sh[3]) * (1.f / DM);
    float d0 = v0 - mu, d1 = v1 - mu, d2 = v2 - mu;
    float q = d0*d0 + d1*d1 + d2*d2;
    __syncthreads();
#pragma unroll
    for (int o = 16; o > 0; o >>= 1) q += __shfl_xor_sync(0xffffffffu, q, o);
    if ((tid & 31) == 0) sh[tid >> 5] = q;
    __syncthreads();
    float var = (sh[0] + sh[1] + sh[2] + sh[3]) * (1.f / DM);
    float rs = rsqrtf(var + 1e-5f);
    float* yr = y + (size_t)row * DM;
    yr[tid]       = rnd32(d0 * rs * g[tid]       + b[tid]);
    yr[tid + 128] = rnd32(d1 * rs * g[tid + 128] + b[tid + 128]);
    yr[tid + 256] = rnd32(d2 * rs * g[tid + 256] + b[tid + 256]);
}

// ---------------- conv1d + SiLU (fp32 output: scan + fp32 xproj consume it) ----------------
__global__ void conv_silu(const float* __restrict__ xz, const float* __restrict__ w,
                          const float* __restrict__ bias, float* __restrict__ u)
{
    int idx = blockIdx.x * blockDim.x + threadIdx.x;
    if (idx >= 2 * MROWS * DI) return;
    int c   = idx % DI;
    int m   = (idx / DI) % MROWS;
    int dir = idx / (DI * MROWS);
    int l = m % LSEQ;
    int mbase = m - l;
    const float* xzd = xz + (size_t)dir * MROWS * 2 * DI;
    const float* wp = w + ((size_t)dir * DI + c) * 4;
    float w0 = wp[0], w1 = wp[1], w2 = wp[2], w3 = wp[3];
    float acc = bias[dir * DI + c];
#pragma unroll
    for (int k = 0; k < 4; k++) {
        int ls = dir ? (l + 3 - k) : (l - 3 + k);
        if (ls >= 0 && ls < LSEQ) {
            float wv = (k == 0) ? w0 : (k == 1) ? w1 : (k == 2) ? w2 : w3;
            acc += wv * xzd[(size_t)(mbase + ls) * 2 * DI + c];
        }
    }
    u[idx] = acc / (1.f + __expf(-acc));
}

// ---------------- selective scan (fp32 inputs; y output rounded for out-proj) ----------------
__global__ void __launch_bounds__(256) scan_kernel(
    const float* __restrict__ dt, const float* __restrict__ u,
    const float* __restrict__ dbc, const float* __restrict__ xz,
    const float* __restrict__ A_log, const float* __restrict__ Dp,
    float* __restrict__ y)
{
    const int c   = blockIdx.x * 256 + threadIdx.x;
    const int b   = blockIdx.y;
    const int dir = blockIdx.z;

    __shared__ float Bsh[LSEQ][DS];
    __shared__ float Csh[LSEQ][DS];
    const float* dbcb = dbc + ((size_t)dir * MROWS + (size_t)b * LSEQ) * DBCN;
    for (int i = threadIdx.x; i < LSEQ * 2 * DS; i += 256) {
        int l = i >> 5, j = i & 31;
        float v = dbcb[(size_t)l * DBCN + DTR + j];
        if (j < DS) Bsh[l][j] = v; else Csh[l][j - DS] = v;
    }
    __syncthreads();

    float a[DS];
    const float* ap = A_log + ((size_t)dir * DI + c) * DS;
#pragma unroll
    for (int n = 0; n < DS; n++) a[n] = -__expf(ap[n]);
    const float dp = Dp[dir * DI + c];

    float h[DS];
#pragma unroll
    for (int n = 0; n < DS; n++) h[n] = 0.f;

    const float* dtb = dt + ((size_t)dir * MROWS + (size_t)b * LSEQ) * DI + c;
    const float* ub  = u  + ((size_t)dir * MROWS + (size_t)b * LSEQ) * DI + c;
    const float* zb  = xz + ((size_t)dir * MROWS + (size_t)b * LSEQ) * 2 * DI + DI + c;
    float* yb = y + ((size_t)b * LSEQ) * 2 * DI + (size_t)dir * DI + c;

    for (int t = 0; t < LSEQ; t++) {
        int l = dir ? (LSEQ - 1 - t) : t;
        float dtv = dtb[(size_t)l * DI];
        float uv  = ub [(size_t)l * DI];
        float du = dtv * uv;
        float acc = 0.f;
#pragma unroll
        for (int n = 0; n < DS; n++) {
            h[n] = __expf(dtv * a[n]) * h[n] + du * Bsh[l][n];
            acc = fmaf(h[n], Csh[l][n], acc);
        }
        float yv = acc + dp * uv;
        float zv = zb[(size_t)l * 2 * DI];
        yb[(size_t)l * 2 * DI] = rnd32(yv * (zv / (1.f + __expf(-zv))));
    }
}

// ---------------- final LN + pool + heads ----------------
__global__ void __launch_bounds__(384) final_head(
    const float* __restrict__ x, const float* __restrict__ g, const float* __restrict__ bb,
    const float* __restrict__ wdev, const float* __restrict__ bdev,
    const float* __restrict__ wdist, const float* __restrict__ bdist,
    float* __restrict__ out)
{
    const int b = blockIdx.x;
    const int tid = threadIdx.x;
    __shared__ float sh[12];
    __shared__ float pooled_s[DM];
    float pooled = 0.f;
    for (int l = 0; l < LSEQ; l++) {
        float v = x[((size_t)b * LSEQ + l) * DM + tid];
        float s = v;
#pragma unroll
        for (int o = 16; o > 0; o >>= 1) s += __shfl_xor_sync(0xffffffffu, s, o);
        if ((tid & 31) == 0) sh[tid >> 5] = s;
        __syncthreads();
        float mu = 0.f;
#pragma unroll
        for (int w = 0; w < 12; w++) mu += sh[w];
        mu *= (1.f / DM);
        float d = v - mu;
        float q = d * d;
        __syncthreads();
#pragma unroll
        for (int o = 16; o > 0; o >>= 1) q += __shfl_xor_sync(0xffffffffu, q, o);
        if ((tid & 31) == 0) sh[tid >> 5] = q;
        __syncthreads();
        float var = 0.f;
#pragma unroll
        for (int w = 0; w < 12; w++) var += sh[w];
        var *= (1.f / DM);
        float rs = rsqrtf(var + 1e-5f);
        pooled += d * rs * g[tid] + bb[tid];
        __syncthreads();
    }
    pooled_s[tid] = pooled * (1.f / LSEQ);
    __syncthreads();
    if (tid < 7) {
        float s = bdev[tid];
        for (int d = 0; d < DM; d++) s += pooled_s[d] * wdev[d * 7 + tid];
        out[b * 7 + tid] = s;
    } else if (tid < 11) {
        int j = tid - 7;
        float s = bdist[j];
        for (int d = 0; d < DM; d++) s += pooled_s[d] * wdist[d * 4 + j];
        out[BATCHN * 7 + b * 4 + j] = s;
    }
}

// ---------------- im2col (rounded; only patch GEMM consumes it) ----------------
__global__ void im2col_kernel(const float* __restrict__ img)
{
    int idx = blockIdx.x * blockDim.x + threadIdx.x;
    if (idx >= MROWS * 768) return;
    int k = idx % 768;
    int m = idx / 768;
    int b = m / LSEQ, l = m % LSEQ;
    int ph = l / 14, pw = l % 14;
    int ch  = k >> 8;
    int r   = (k >> 4) & 15;
    int col = k & 15;
    g_im2col[idx] = rnd32(img[(((size_t)b * 3 + ch) * 224 + ph * 16 + r) * 224 + pw * 16 + col]);
}

// ---------------- launcher ----------------
extern "C" void kernel_launch(void* const* d_in, const int* in_sizes, int n_in,
                              void* d_out, int out_size)
{
    const float* images  = (const float*)d_in[0];
    const float* patch_w = (const float*)d_in[1];
    const float* patch_b = (const float*)d_in[2];
    const float* pos_emb = (const float*)d_in[3];
    const float* ln_g    = (const float*)d_in[4];
    const float* ln_b    = (const float*)d_in[5];
    const float* in_w    = (const float*)d_in[6];
    const float* conv_w  = (const float*)d_in[7];
    const float* conv_b  = (const float*)d_in[8];
    const float* xproj_w = (const float*)d_in[9];
    const float* dt_w    = (const float*)d_in[10];
    const float* dt_b    = (const float*)d_in[11];
    const float* A_log   = (const float*)d_in[12];
    const float* Dp      = (const float*)d_in[13];
    const float* out_w   = (const float*)d_in[14];
    const float* fln_g   = (const float*)d_in[15];
    const float* fln_b   = (const float*)d_in[16];
    const float* hdev_w  = (const float*)d_in[17];
    const float* hdev_b  = (const float*)d_in[18];
    const float* hdist_w = (const float*)d_in[19];
    const float* hdist_b = (const float*)d_in[20];
    float* out = (float*)d_out;

    float *x, *xn, *im2c, *xz, *u, *dbcv, *dtv, *yv, *inwT, *outwT, *pw;
    cudaGetSymbolAddress((void**)&x,     g_x);
    cudaGetSymbolAddress((void**)&xn,    g_xn);
    cudaGetSymbolAddress((void**)&im2c,  g_im2col);
    cudaGetSymbolAddress((void**)&xz,    g_xz);
    cudaGetSymbolAddress((void**)&u,     g_u);
    cudaGetSymbolAddress((void**)&dbcv,  g_dbc);
    cudaGetSymbolAddress((void**)&dtv,   g_dt);
    cudaGetSymbolAddress((void**)&yv,    g_y);
    cudaGetSymbolAddress((void**)&inwT,  g_inwT);
    cudaGetSymbolAddress((void**)&outwT, g_outwT);
    cudaGetSymbolAddress((void**)&pw,    g_pw);

    const int SMEM_N128 = 1024 + 4 * (16384 + 128 * 128);  // 132096
    cudaFuncSetAttribute(mma_gemm<128,0>, cudaFuncAttributeMaxDynamicSharedMemorySize, SMEM_N128);
    cudaFuncSetAttribute(mma_gemm<128,2>, cudaFuncAttributeMaxDynamicSharedMemorySize, SMEM_N128);
    cudaFuncSetAttribute(mma_gemm<128,3>, cudaFuncAttributeMaxDynamicSharedMemorySize, SMEM_N128);

    const int MT = MROWS / 128;  // 49

    // ---- weight packing (rounded to tf32) ----
    transpose_rnd<<<dim3(384/32, 1536/32, 24), 256>>>(in_w, inwT, 384, 1536);
    transpose_rnd<<<dim3(1536/32, 384/32, 12), 256>>>(out_w, outwT, 1536, 384);
    round_copy<<<(DM*768 + 255)/256, 256>>>(patch_w, pw, DM*768);

    // ---- patch embedding ----
    im2col_kernel<<<(MROWS * 768 + 255) / 256, 256>>>(images);
    mma_gemm<128,3><<<dim3(DM/128, MT, 1), 256, SMEM_N128>>>(
        im2c, 768, 0,  pw, 768, 0,  x, DM, 0,  768/32,  patch_b, pos_emb);

    for (int layer = 0; layer < DEPTH; layer++) {
        ln_kernel<<<MROWS, 128>>>(x, xn, ln_g + (size_t)layer * DM, ln_b + (size_t)layer * DM);

        // xz[dir] = xn @ in_w[layer,dir]^T  (tf32 MMA)
        mma_gemm<128,0><<<dim3(2*DI/128, MT, 2), 256, SMEM_N128>>>(
            xn, DM, 0,
            inwT + (size_t)layer * 2 * 2*DI * DM, DM, (long)2*DI * DM,
            xz, 2*DI, (long)MROWS * 2*DI,
            DM/32, nullptr, nullptr);

        conv_silu<<<(2 * MROWS * DI + 255) / 256, 256>>>(
            xz, conv_w + (size_t)layer * 2 * DI * 4, conv_b + (size_t)layer * 2 * DI, u);

        // dbc = u @ xproj_w  (fp32 SIMT; scan needs full precision)
        sgemm<0><<<dim3(1, MT, 2), 256>>>(
            u, xproj_w + (size_t)layer * 2 * DI * DBCN, dbcv,
            MROWS, DBCN, DI, DI,
            (long)MROWS * DI, (long)DI * DBCN, (long)MROWS * DBCN, nullptr, 0);

        // dt = softplus(dbc[:, :24] @ dt_w + dt_b)  (fp32 SIMT)
        sgemm<1><<<dim3(DI / 64, MT, 2), 256>>>(
            dbcv, dt_w + (size_t)layer * 2 * DTR * DI, dtv,
            MROWS, DI, DTR, DBCN,
            (long)MROWS * DBCN, (long)DTR * DI, (long)MROWS * DI,
            dt_b + (size_t)layer * 2 * DI, (long)DI);

        scan_kernel<<<dim3(3, BATCHN, 2), 256>>>(
            dtv, u, dbcv, xz,
            A_log + (size_t)layer * 2 * DI * DS, Dp + (size_t)layer * 2 * DI, yv);

        // x += y @ out_w[layer]  (tf32 MMA, dirs stacked K=1536)
        mma_gemm<128,2><<<dim3(DM/128, MT, 1), 256, SMEM_N128>>>(
            yv, 2*DI, 0,
            outwT + (size_t)layer * DM * 2*DI, 2*DI, 0,
            x, DM, 0,
            2*DI/32, nullptr, x);
    }

    final_head<<<BATCHN, 384>>>(x, fln_g, fln_b, hdev_w, hdev_b, hdist_w, hdist_b, out);
    (void)in_sizes; (void)n_in; (void)out_size;
}

// round 6
// speedup vs baseline: 2.1473x; 1.1001x over previous
#include <cuda_runtime.h>
#include <cuda_bf16.h>
#include <math.h>
#include <stdint.h>

#define BATCHN 32
#define LSEQ   196
#define DM     384
#define DI     768
#define DS     16
#define DTR    24
#define DBCN   56
#define DEPTH  12
#define MROWS  (BATCHN*LSEQ)   // 6272

#if defined(__CUDA_ARCH__) && (defined(__CUDA_ARCH_FEAT_SM103_ALL) || defined(__CUDA_ARCH_SPECIFIC__))
#define HAS_TC 1
#else
#define HAS_TC 0
#endif

typedef __nv_bfloat16 bf16;

// ---------------- scratch ----------------
__device__ __align__(256) float g_x  [MROWS*DM];
__device__ __align__(256) float g_xz [2*MROWS*2*DI];
__device__ __align__(256) float g_dbc[2*MROWS*DBCN];
__device__ __align__(256) float g_dt [2*MROWS*DI];

__device__ __align__(256) bf16 g_xn_h[MROWS*DM],    g_xn_l[MROWS*DM];
__device__ __align__(256) bf16 g_im_h[MROWS*768],   g_im_l[MROWS*768];
__device__ __align__(256) bf16 g_u_h [2*MROWS*DI],  g_u_l [2*MROWS*DI];
__device__ __align__(256) bf16 g_y_h [MROWS*2*DI],  g_y_l [MROWS*2*DI];
__device__ __align__(256) bf16 g_inw_h [DEPTH*2*2*DI*DM], g_inw_l [DEPTH*2*2*DI*DM]; // [l*2+d][1536][384]
__device__ __align__(256) bf16 g_outw_h[DEPTH*DM*2*DI],   g_outw_l[DEPTH*DM*2*DI];   // [l][384][1536]
__device__ __align__(256) bf16 g_xpw_h [DEPTH*2*64*DI],   g_xpw_l [DEPTH*2*64*DI];   // [l*2+d][64][768], rows>=56 zero
__device__ __align__(256) bf16 g_pw_h  [DM*768],          g_pw_l  [DM*768];          // [384][768]

__device__ __forceinline__ void split2(float v, bf16& h, bf16& l) {
    h = __float2bfloat16(v);
    l = __float2bfloat16(v - __bfloat162float(h));
}

#if HAS_TC
__device__ __forceinline__ uint32_t smem_u32(const void* p) {
    uint32_t a;
    asm("{ .reg .u64 t; cvta.to.shared.u64 t, %1; cvt.u32.u64 %0, t; }" : "=r"(a) : "l"(p));
    return a;
}
__device__ __forceinline__ uint32_t elect_one() {
    uint32_t p;
    asm volatile("{ .reg .pred p; elect.sync _|p, 0xFFFFFFFF; selp.b32 %0,1,0,p; }" : "=r"(p));
    return p;
}
#define SWZ(o) ((o) ^ (((o) >> 3) & 0x70))

static __device__ __forceinline__ uint64_t make_desc(uint32_t addr) {
    const uint64_t base =
        (uint64_t(2) << 61) | (uint64_t(1) << 46) | (uint64_t(64) << 32) | (uint64_t(1) << 16);
    return base | ((uint64_t)(addr >> 4) & 0x3FFF);
}

#define MBAR_INIT(a, c) \
    asm volatile("mbarrier.init.shared.b64 [%0], %1;" :: "r"(a), "r"(c) : "memory")
#define MBAR_INVAL(a) \
    asm volatile("mbarrier.inval.shared.b64 [%0];" :: "r"(a) : "memory")
#define MBAR_WAIT(a, ph) do {                                            \
    uint32_t _m = (a); uint32_t _p = (ph); uint32_t _d;                  \
    asm volatile("{ .reg .pred p; mbarrier.try_wait.parity.acquire.cta.shared::cta.b64 p,[%1],%2; selp.b32 %0,1,0,p; }" \
        : "=r"(_d) : "r"(_m), "r"(_p) : "memory");                       \
    if (!_d) {                                                           \
        asm volatile("{ .reg .pred P1; W%=: mbarrier.try_wait.parity.acquire.cta.shared::cta.b64 P1,[%0],%1,0x989680; @P1 bra.uni D%=; bra.uni W%=; D%=: }" \
            :: "r"(_m), "r"(_p) : "memory");                             \
    } } while (0)

#define CP_ASYNC16(dst, src) \
    asm volatile("cp.async.cg.shared.global [%0], [%1], 16;" :: "r"(dst), "l"(src) : "memory")
#define CP_COMMIT() asm volatile("cp.async.commit_group;" ::: "memory")
// 3-stage ring: before iter s, 3+s groups committed; step s lives in group s+2
// (prologue for s<3). wait_group 1 -> groups 1..s+2 complete.
#define CP_WAIT1()  asm volatile("cp.async.wait_group 1;" ::: "memory")

__device__ __forceinline__ void tc_alloc(uint32_t smem_dst, uint32_t ncols) {
    asm volatile("tcgen05.alloc.cta_group::1.sync.aligned.shared::cta.b32 [%0], %1;"
                 :: "r"(smem_dst), "r"(ncols) : "memory");
}
__device__ __forceinline__ void tc_relinq() {
    asm volatile("tcgen05.relinquish_alloc_permit.cta_group::1.sync.aligned;");
}
__device__ __forceinline__ void tc_dealloc(uint32_t tmem, uint32_t ncols) {
    asm volatile("tcgen05.dealloc.cta_group::1.sync.aligned.b32 %0, %1;" :: "r"(tmem), "r"(ncols));
}
__device__ __forceinline__ void tc_commit(uint32_t mbar) {
    asm volatile("tcgen05.commit.cta_group::1.mbarrier::arrive::one.shared::cluster.b64 [%0];"
                 :: "r"(mbar) : "memory");
}
__device__ __forceinline__ void mma_bf16(uint32_t d, uint64_t ad, uint64_t bd, uint32_t idesc, bool acc) {
    uint32_t en = acc ? 1u : 0u, z = 0u;
    asm volatile(
        "{ .reg .pred p; setp.ne.u32 p, %5, 0;"
        " tcgen05.mma.cta_group::1.kind::f16 [%0], %1, %2, %3, {%4,%4,%4,%4}, p; }"
        :: "r"(d), "l"(ad), "l"(bd), "r"(idesc), "r"(z), "r"(en) : "memory");
}
#define TC_LD_X32(r, a)                                                     \
    asm volatile("tcgen05.ld.sync.aligned.32x32b.x32.b32 "                  \
        "{%0,%1,%2,%3,%4,%5,%6,%7,%8,%9,%10,%11,%12,%13,%14,%15,"           \
        "%16,%17,%18,%19,%20,%21,%22,%23,%24,%25,%26,%27,%28,%29,%30,%31}, [%32];" \
        : "=r"((r)[0]),"=r"((r)[1]),"=r"((r)[2]),"=r"((r)[3]),"=r"((r)[4]),"=r"((r)[5]),"=r"((r)[6]),"=r"((r)[7]), \
          "=r"((r)[8]),"=r"((r)[9]),"=r"((r)[10]),"=r"((r)[11]),"=r"((r)[12]),"=r"((r)[13]),"=r"((r)[14]),"=r"((r)[15]), \
          "=r"((r)[16]),"=r"((r)[17]),"=r"((r)[18]),"=r"((r)[19]),"=r"((r)[20]),"=r"((r)[21]),"=r"((r)[22]),"=r"((r)[23]), \
          "=r"((r)[24]),"=r"((r)[25]),"=r"((r)[26]),"=r"((r)[27]),"=r"((r)[28]),"=r"((r)[29]),"=r"((r)[30]),"=r"((r)[31]) \
        : "r"(a))
#define TC_WAIT_LD() asm volatile("tcgen05.wait::ld.sync.aligned;" ::: "memory")
#define TC_FENCE_AFTER() asm volatile("tcgen05.fence::after_thread_sync;" ::: "memory")
#endif  // HAS_TC

// =====================================================================
// bf16 split-precision tcgen05 GEMM, 3-stage cp.async ring, 256 threads.
// C = (Ah+Al)[M,K] @ ((Bh+Bl)[N,K])^T  ≈ Ah·Bh + Al·Bh + Ah·Bl  (fp32 accum)
// K-step = 64 elements (128B rows, SW128). S = K/64 (any S>=1).
// EPI: 0 plain, 2 v+res, 3 v+bias[col]+res[(m%L)*ldc+col]
// =====================================================================
template<int NT, int EPI>
__global__ void __launch_bounds__(256, 1) mma_gemm(
    const bf16* __restrict__ Ah, const bf16* __restrict__ Al, int lda, long sA,
    const bf16* __restrict__ Bh, const bf16* __restrict__ Bl, int ldb, long sB,
    float* __restrict__ C, int ldc, long sC, int Ncols,
    int S,
    const float* __restrict__ bias,
    const float* __restrict__ res)
{
    const int tid = threadIdx.x;
    const int m0 = blockIdx.y * 128, n0 = blockIdx.x * NT;
    Ah += (size_t)blockIdx.z * sA;  Al += (size_t)blockIdx.z * sA;
    Bh += (size_t)blockIdx.z * sB;  Bl += (size_t)blockIdx.z * sB;
    C  += (size_t)blockIdx.z * sC;

#if HAS_TC
    extern __shared__ char smem[];
    const uint32_t sb = smem_u32(smem);
    const int wid = tid >> 5, lane = tid & 31;
    constexpr int ABYTES = 128 * 128;          // 128 rows x 64 bf16
    constexpr int BBYTES = NT * 128;
    constexpr int STAGE  = 2 * ABYTES + 2 * BBYTES;

    if (tid == 0) {
#pragma unroll
        for (int i = 0; i < 3; i++) MBAR_INIT(sb + 8 + i * 8, 1);
    }
    if (wid == 0) { tc_alloc(sb, NT); tc_relinq(); }
    __syncthreads();
    uint32_t tmem;
    asm volatile("ld.shared.b32 %0, [%1];" : "=r"(tmem) : "r"(sb));

    // idesc kind::f16: dtype=F32, atype=btype=BF16, N, M=128
    const uint32_t idesc = 0x10u | (1u << 7) | (1u << 10)
                         | ((uint32_t)(NT / 8) << 17) | (8u << 24);

    auto stage_load = [&](int r, int step) {
        const int k0 = step << 6;  // 64 bf16 per step
        const uint32_t ah = sb + 1024 + r * STAGE;
        const uint32_t al = ah + ABYTES;
        const uint32_t bh = al + ABYTES;
        const uint32_t bl = bh + BBYTES;
#pragma unroll
        for (int i = 0; i < 4; i++) {   // 1024 chunks / 256 thr
            int c = i * 256 + tid; int row = c >> 3, q = c & 7;
            uint32_t so = SWZ(row * 128 + q * 16);
            size_t go = (size_t)(m0 + row) * lda + k0 + q * 8;
            CP_ASYNC16(ah + so, Ah + go);
            CP_ASYNC16(al + so, Al + go);
        }
#pragma unroll
        for (int i = 0; i < NT / 32; i++) {
            int c = i * 256 + tid; int row = c >> 3, q = c & 7;
            uint32_t so = SWZ(row * 128 + q * 16);
            size_t go = (size_t)(n0 + row) * ldb + k0 + q * 8;
            CP_ASYNC16(bh + so, Bh + go);
            CP_ASYNC16(bl + so, Bl + go);
        }
    };

    // prologue: stages 0..2 <- steps 0..2 (commit empties beyond S)
#pragma unroll
    for (int p = 0; p < 3; p++) { if (p < S) stage_load(p, p); CP_COMMIT(); }

    int ph[3] = {0, 0, 0};
    for (int s = 0; s < S; s++) {
        CP_WAIT1();
        asm volatile("fence.proxy.async.shared::cta;" ::: "memory");
        __syncthreads();
        if (wid == 0 && elect_one()) {
            const int st = s % 3;
            const uint32_t ah = sb + 1024 + st * STAGE;
            uint64_t adh = make_desc(ah);
            uint64_t adl = make_desc(ah + ABYTES);
            uint64_t bdh = make_desc(ah + 2 * ABYTES);
            uint64_t bdl = make_desc(ah + 2 * ABYTES + BBYTES);
#pragma unroll
            for (int sl = 0; sl < 4; sl++)
                mma_bf16(tmem, adh + sl * 2, bdh + sl * 2, idesc, (s > 0) || (sl > 0));
#pragma unroll
            for (int sl = 0; sl < 4; sl++)
                mma_bf16(tmem, adl + sl * 2, bdh + sl * 2, idesc, true);
#pragma unroll
            for (int sl = 0; sl < 4; sl++)
                mma_bf16(tmem, adh + sl * 2, bdl + sl * 2, idesc, true);
            tc_commit(sb + 8 + (s % 3) * 8);
        }
        // refill stage holding step s-1 with step s+2, after MMA(s-1) done
        if (s >= 1 && s + 2 < S) {
            const int r = (s + 2) % 3;   // == (s-1)%3
            MBAR_WAIT(sb + 8 + r * 8, ph[r]); ph[r] ^= 1;
            stage_load(r, s + 2);
        }
        CP_COMMIT();
    }
    // commit is cumulative: waiting the last one covers all prior MMAs
    MBAR_WAIT(sb + 8 + ((S - 1) % 3) * 8, ph[(S - 1) % 3]);
    TC_FENCE_AFTER();

    const int subp = wid & 3, half = wid >> 2;
#pragma unroll
    for (int ch = 0; ch < NT / 64; ch++) {
        const int chunk = half * (NT / 64) + ch;
        uint32_t r[32];
        TC_LD_X32(r, tmem + chunk * 32);
        TC_WAIT_LD();
        const int row = m0 + subp * 32 + lane;
        const int col0 = n0 + chunk * 32;
        float* cp = C + (size_t)row * ldc + col0;
        float vals[32];
#pragma unroll
        for (int j = 0; j < 32; j++) {
            float v = __uint_as_float(r[j]);
            const int col = col0 + j;
            if (EPI == 2) v += res[(size_t)row * ldc + col];
            if (EPI == 3) v += bias[col] + res[(size_t)(row % LSEQ) * ldc + col];
            vals[j] = v;
        }
        if (col0 + 31 < Ncols) {
#pragma unroll
            for (int g = 0; g < 8; g++)
                *(float4*)(cp + g * 4) =
                    make_float4(vals[4*g], vals[4*g+1], vals[4*g+2], vals[4*g+3]);
        } else {
#pragma unroll
            for (int j = 0; j < 32; j++)
                if (col0 + j < Ncols) cp[j] = vals[j];
        }
    }
    __syncthreads();
    if (tid == 0) {
#pragma unroll
        for (int i = 0; i < 3; i++) MBAR_INVAL(sb + 8 + i * 8);
    }
    if (wid == 0) tc_dealloc(tmem, NT);
#else
    // SIMT fallback (non-arch-specific pass; never runs on GB300)
    if (tid >= 128) return;
    const int row = m0 + tid;
    const int K = S * 64;
    for (int n = 0; n < NT; n++) {
        const int col = n0 + n;
        if (col >= Ncols) break;
        float acc = 0.f;
        for (int k = 0; k < K; k++) {
            float a = __bfloat162float(Ah[(size_t)row * lda + k]) +
                      __bfloat162float(Al[(size_t)row * lda + k]);
            float b = __bfloat162float(Bh[(size_t)col * ldb + k]) +
                      __bfloat162float(Bl[(size_t)col * ldb + k]);
            acc = fmaf(a, b, acc);
        }
        float v = acc;
        if (EPI == 2) v += res[(size_t)row * ldc + col];
        if (EPI == 3) v += bias[col] + res[(size_t)(row % LSEQ) * ldc + col];
        C[(size_t)row * ldc + col] = v;
    }
#endif
}

// ---- transpose + zero-pad + bf16-split: out[z][i][j] = split(in[z][j][i]) ----
__global__ void __launch_bounds__(256) transpose_split(
    const float* __restrict__ in, bf16* __restrict__ oh, bf16* __restrict__ ol,
    int R, int C, int OR_, int OC)
{
    __shared__ float t[32][33];
    const int z = blockIdx.z;
    in += (size_t)z * R * C;
    oh += (size_t)z * OR_ * OC;
    ol += (size_t)z * OR_ * OC;
    const int j0 = blockIdx.x * 32;  // input row base
    const int i0 = blockIdx.y * 32;  // input col base
    const int tx = threadIdx.x & 31, ty = threadIdx.x >> 5;
#pragma unroll
    for (int k = 0; k < 4; k++) {
        int rin = j0 + ty + k * 8, cin = i0 + tx;
        t[ty + k * 8][tx] = (rin < R && cin < C) ? in[(size_t)rin * C + cin] : 0.f;
    }
    __syncthreads();
#pragma unroll
    for (int k = 0; k < 4; k++) {
        int orow = i0 + ty + k * 8, ocol = j0 + tx;
        if (orow < OR_ && ocol < OC) {
            bf16 h, l; split2(t[tx][ty + k * 8], h, l);
            oh[(size_t)orow * OC + ocol] = h;
            ol[(size_t)orow * OC + ocol] = l;
        }
    }
}

// ---- split-copy (patch_w already [N][K]) ----
__global__ void split_copy(const float* __restrict__ in,
                           bf16* __restrict__ oh, bf16* __restrict__ ol, int n)
{
    int i = blockIdx.x * blockDim.x + threadIdx.x;
    if (i < n) { bf16 h, l; split2(in[i], h, l); oh[i] = h; ol[i] = l; }
}

// ---------------- fp32 SGEMM (dt only) ----------------
__global__ void __launch_bounds__(256) sgemm_sp(
    const float* __restrict__ A, const float* __restrict__ B, float* __restrict__ C,
    int M, int N, int K, int lda,
    long sA, long sB, long sC,
    const float* __restrict__ bias, long sBias)
{
    A += (size_t)blockIdx.z * sA;
    B += (size_t)blockIdx.z * sB;
    C += (size_t)blockIdx.z * sC;
    bias += (size_t)blockIdx.z * sBias;

    const int tid = threadIdx.x;
    const int tx = tid & 15, ty = tid >> 4;
    const int m0 = blockIdx.y * 128;
    const int n0 = blockIdx.x * 64;

    __shared__ float As[16][132];
    __shared__ float Bs[16][68];

    float acc[8][4];
#pragma unroll
    for (int i = 0; i < 8; i++)
#pragma unroll
        for (int j = 0; j < 4; j++) acc[i][j] = 0.f;

    const int am  = tid >> 1;
    const int akq = (tid & 1) * 8;
    const int bk  = tid >> 4;
    const int bn  = (tid & 15) * 4;

    for (int k0 = 0; k0 < K; k0 += 16) {
        {
            float4 v0 = make_float4(0.f,0.f,0.f,0.f), v1 = v0;
            if (k0 + akq < K) {
                const float* ap = A + (size_t)(m0 + am) * lda + k0 + akq;
                v0 = *(const float4*)(ap);
                v1 = *(const float4*)(ap + 4);
            }
            As[akq+0][am] = v0.x; As[akq+1][am] = v0.y;
            As[akq+2][am] = v0.z; As[akq+3][am] = v0.w;
            As[akq+4][am] = v1.x; As[akq+5][am] = v1.y;
            As[akq+6][am] = v1.z; As[akq+7][am] = v1.w;
        }
        {
            float4 v = make_float4(0.f,0.f,0.f,0.f);
            if (k0 + bk < K) v = *(const float4*)(B + (size_t)(k0 + bk) * N + n0 + bn);
            *(float4*)&Bs[bk][bn] = v;
        }
        __syncthreads();
#pragma unroll
        for (int kk = 0; kk < 16; kk++) {
            float4 a0 = *(const float4*)&As[kk][ty*8];
            float4 a1 = *(const float4*)&As[kk][ty*8+4];
            float4 b4 = *(const float4*)&Bs[kk][tx*4];
            float a[8] = {a0.x,a0.y,a0.z,a0.w,a1.x,a1.y,a1.z,a1.w};
            float bb[4] = {b4.x,b4.y,b4.z,b4.w};
#pragma unroll
            for (int i = 0; i < 8; i++)
#pragma unroll
                for (int j = 0; j < 4; j++)
                    acc[i][j] = fmaf(a[i], bb[j], acc[i][j]);
        }
        __syncthreads();
    }
#pragma unroll
    for (int i = 0; i < 8; i++) {
        int r = m0 + ty*8 + i;
#pragma unroll
        for (int j = 0; j < 4; j++) {
            int col = n0 + tx*4 + j;
            float v = acc[i][j] + bias[col];
            C[(size_t)r * N + col] = (v > 0.f) ? v + log1pf(__expf(-v)) : log1pf(__expf(v));
        }
    }
}

// ---------------- LayerNorm -> bf16 hi/lo ----------------
__global__ void __launch_bounds__(128) ln_kernel(
    const float* __restrict__ x, bf16* __restrict__ yh, bf16* __restrict__ yl,
    const float* __restrict__ g, const float* __restrict__ b)
{
    const int row = blockIdx.x;
    const int tid = threadIdx.x;
    const float* xr = x + (size_t)row * DM;
    float v0 = xr[tid], v1 = xr[tid + 128], v2 = xr[tid + 256];
    __shared__ float sh[4];
    float s = v0 + v1 + v2;
#pragma unroll
    for (int o = 16; o > 0; o >>= 1) s += __shfl_xor_sync(0xffffffffu, s, o);
    if ((tid & 31) == 0) sh[tid >> 5] = s;
    __syncthreads();
    float mu = (sh[0] + sh[1] + sh[2] + sh[3]) * (1.f / DM);
    float d0 = v0 - mu, d1 = v1 - mu, d2 = v2 - mu;
    float q = d0*d0 + d1*d1 + d2*d2;
    __syncthreads();
#pragma unroll
    for (int o = 16; o > 0; o >>= 1) q += __shfl_xor_sync(0xffffffffu, q, o);
    if ((tid & 31) == 0) sh[tid >> 5] = q;
    __syncthreads();
    float var = (sh[0] + sh[1] + sh[2] + sh[3]) * (1.f / DM);
    float rs = rsqrtf(var + 1e-5f);
    bf16 h, l;
    size_t base = (size_t)row * DM;
    split2(d0 * rs * g[tid]       + b[tid],       h, l); yh[base + tid]       = h; yl[base + tid]       = l;
    split2(d1 * rs * g[tid + 128] + b[tid + 128], h, l); yh[base + tid + 128] = h; yl[base + tid + 128] = l;
    split2(d2 * rs * g[tid + 256] + b[tid + 256], h, l); yh[base + tid + 256] = h; yl[base + tid + 256] = l;
}

// ---------------- conv1d + SiLU -> u hi/lo ----------------
__global__ void conv_silu(const float* __restrict__ xz, const float* __restrict__ w,
                          const float* __restrict__ bias,
                          bf16* __restrict__ uh, bf16* __restrict__ ul)
{
    int idx = blockIdx.x * blockDim.x + threadIdx.x;
    if (idx >= 2 * MROWS * DI) return;
    int c   = idx % DI;
    int m   = (idx / DI) % MROWS;
    int dir = idx / (DI * MROWS);
    int l = m % LSEQ;
    int mbase = m - l;
    const float* xzd = xz + (size_t)dir * MROWS * 2 * DI;
    const float* wp = w + ((size_t)dir * DI + c) * 4;
    float w0 = wp[0], w1 = wp[1], w2 = wp[2], w3 = wp[3];
    float acc = bias[dir * DI + c];
#pragma unroll
    for (int k = 0; k < 4; k++) {
        int ls = dir ? (l + 3 - k) : (l - 3 + k);
        if (ls >= 0 && ls < LSEQ) {
            float wv = (k == 0) ? w0 : (k == 1) ? w1 : (k == 2) ? w2 : w3;
            acc += wv * xzd[(size_t)(mbase + ls) * 2 * DI + c];
        }
    }
    float uv = acc / (1.f + __expf(-acc));
    bf16 h, lo; split2(uv, h, lo);
    uh[idx] = h; ul[idx] = lo;
}

// ---------------- selective scan -> y hi/lo ----------------
__global__ void __launch_bounds__(256) scan_kernel(
    const float* __restrict__ dt,
    const bf16* __restrict__ uh, const bf16* __restrict__ ul,
    const float* __restrict__ dbc, const float* __restrict__ xz,
    const float* __restrict__ A_log, const float* __restrict__ Dp,
    bf16* __restrict__ yh, bf16* __restrict__ yl)
{
    const int c   = blockIdx.x * 256 + threadIdx.x;
    const int b   = blockIdx.y;
    const int dir = blockIdx.z;

    __shared__ float Bsh[LSEQ][DS];
    __shared__ float Csh[LSEQ][DS];
    const float* dbcb = dbc + ((size_t)dir * MROWS + (size_t)b * LSEQ) * DBCN;
    for (int i = threadIdx.x; i < LSEQ * 2 * DS; i += 256) {
        int l = i >> 5, j = i & 31;
        float v = dbcb[(size_t)l * DBCN + DTR + j];
        if (j < DS) Bsh[l][j] = v; else Csh[l][j - DS] = v;
    }
    __syncthreads();

    float a[DS];
    const float* ap = A_log + ((size_t)dir * DI + c) * DS;
#pragma unroll
    for (int n = 0; n < DS; n++) a[n] = -__expf(ap[n]);
    const float dp = Dp[dir * DI + c];

    float h[DS];
#pragma unroll
    for (int n = 0; n < DS; n++) h[n] = 0.f;

    const size_t ubase = ((size_t)dir * MROWS + (size_t)b * LSEQ) * DI + c;
    const float* dtb = dt + ubase;
    const float* zb  = xz + ((size_t)dir * MROWS + (size_t)b * LSEQ) * 2 * DI + DI + c;
    const size_t ybase = ((size_t)b * LSEQ) * 2 * DI + (size_t)dir * DI + c;

    for (int t = 0; t < LSEQ; t++) {
        int l = dir ? (LSEQ - 1 - t) : t;
        float dtv = dtb[(size_t)l * DI];
        float uv  = __bfloat162float(uh[ubase + (size_t)l * DI]) +
                    __bfloat162float(ul[ubase + (size_t)l * DI]);
        float du = dtv * uv;
        float acc = 0.f;
#pragma unroll
        for (int n = 0; n < DS; n++) {
            h[n] = __expf(dtv * a[n]) * h[n] + du * Bsh[l][n];
            acc = fmaf(h[n], Csh[l][n], acc);
        }
        float yv = acc + dp * uv;
        float zv = zb[(size_t)l * 2 * DI];
        float out = yv * (zv / (1.f + __expf(-zv)));
        bf16 hh, ll; split2(out, hh, ll);
        yh[ybase + (size_t)l * 2 * DI] = hh;
        yl[ybase + (size_t)l * 2 * DI] = ll;
    }
}

// ---------------- final LN + pool + heads ----------------
__global__ void __launch_bounds__(384) final_head(
    const float* __restrict__ x, const float* __restrict__ g, const float* __restrict__ bb,
    const float* __restrict__ wdev, const float* __restrict__ bdev,
    const float* __restrict__ wdist, const float* __restrict__ bdist,
    float* __restrict__ out)
{
    const int b = blockIdx.x;
    const int tid = threadIdx.x;
    __shared__ float sh[12];
    __shared__ float pooled_s[DM];
    float pooled = 0.f;
    for (int l = 0; l < LSEQ; l++) {
        float v = x[((size_t)b * LSEQ + l) * DM + tid];
        float s = v;
#pragma unroll
        for (int o = 16; o > 0; o >>= 1) s += __shfl_xor_sync(0xffffffffu, s, o);
        if ((tid & 31) == 0) sh[tid >> 5] = s;
        __syncthreads();
        float mu = 0.f;
#pragma unroll
        for (int w = 0; w < 12; w++) mu += sh[w];
        mu *= (1.f / DM);
        float d = v - mu;
        float q = d * d;
        __syncthreads();
#pragma unroll
        for (int o = 16; o > 0; o >>= 1) q += __shfl_xor_sync(0xffffffffu, q, o);
        if ((tid & 31) == 0) sh[tid >> 5] = q;
        __syncthreads();
        float var = 0.f;
#pragma unroll
        for (int w = 0; w < 12; w++) var += sh[w];
        var *= (1.f / DM);
        float rs = rsqrtf(var + 1e-5f);
        pooled += d * rs * g[tid] + bb[tid];
        __syncthreads();
    }
    pooled_s[tid] = pooled * (1.f / LSEQ);
    __syncthreads();
    if (tid < 7) {
        float s = bdev[tid];
        for (int d = 0; d < DM; d++) s += pooled_s[d] * wdev[d * 7 + tid];
        out[b * 7 + tid] = s;
    } else if (tid < 11) {
        int j = tid - 7;
        float s = bdist[j];
        for (int d = 0; d < DM; d++) s += pooled_s[d] * wdist[d * 4 + j];
        out[BATCHN * 7 + b * 4 + j] = s;
    }
}

// ---------------- im2col -> bf16 hi/lo ----------------
__global__ void im2col_kernel(const float* __restrict__ img)
{
    int idx = blockIdx.x * blockDim.x + threadIdx.x;
    if (idx >= MROWS * 768) return;
    int k = idx % 768;
    int m = idx / 768;
    int b = m / LSEQ, l = m % LSEQ;
    int ph = l / 14, pw = l % 14;
    int ch  = k >> 8;
    int r   = (k >> 4) & 15;
    int col = k & 15;
    float v = img[(((size_t)b * 3 + ch) * 224 + ph * 16 + r) * 224 + pw * 16 + col];
    bf16 h, lo; split2(v, h, lo);
    g_im_h[idx] = h; g_im_l[idx] = lo;
}

// ---------------- launcher ----------------
extern "C" void kernel_launch(void* const* d_in, const int* in_sizes, int n_in,
                              void* d_out, int out_size)
{
    const float* images  = (const float*)d_in[0];
    const float* patch_w = (const float*)d_in[1];
    const float* patch_b = (const float*)d_in[2];
    const float* pos_emb = (const float*)d_in[3];
    const float* ln_g    = (const float*)d_in[4];
    const float* ln_b    = (const float*)d_in[5];
    const float* in_w    = (const float*)d_in[6];
    const float* conv_w  = (const float*)d_in[7];
    const float* conv_b  = (const float*)d_in[8];
    const float* xproj_w = (const float*)d_in[9];
    const float* dt_w    = (const float*)d_in[10];
    const float* dt_b    = (const float*)d_in[11];
    const float* A_log   = (const float*)d_in[12];
    const float* Dp      = (const float*)d_in[13];
    const float* out_w   = (const float*)d_in[14];
    const float* fln_g   = (const float*)d_in[15];
    const float* fln_b   = (const float*)d_in[16];
    const float* hdev_w  = (const float*)d_in[17];
    const float* hdev_b  = (const float*)d_in[18];
    const float* hdist_w = (const float*)d_in[19];
    const float* hdist_b = (const float*)d_in[20];
    float* out = (float*)d_out;

    float *x, *xz, *dbcv, *dtv;
    bf16 *xn_h, *xn_l, *im_h, *im_l, *u_h, *u_l, *y_h, *y_l;
    bf16 *inw_h, *inw_l, *outw_h, *outw_l, *xpw_h, *xpw_l, *pw_h, *pw_l;
    cudaGetSymbolAddress((void**)&x,     g_x);
    cudaGetSymbolAddress((void**)&xz,    g_xz);
    cudaGetSymbolAddress((void**)&dbcv,  g_dbc);
    cudaGetSymbolAddress((void**)&dtv,   g_dt);
    cudaGetSymbolAddress((void**)&xn_h,  g_xn_h);  cudaGetSymbolAddress((void**)&xn_l,  g_xn_l);
    cudaGetSymbolAddress((void**)&im_h,  g_im_h);  cudaGetSymbolAddress((void**)&im_l,  g_im_l);
    cudaGetSymbolAddress((void**)&u_h,   g_u_h);   cudaGetSymbolAddress((void**)&u_l,   g_u_l);
    cudaGetSymbolAddress((void**)&y_h,   g_y_h);   cudaGetSymbolAddress((void**)&y_l,   g_y_l);
    cudaGetSymbolAddress((void**)&inw_h, g_inw_h); cudaGetSymbolAddress((void**)&inw_l, g_inw_l);
    cudaGetSymbolAddress((void**)&outw_h,g_outw_h);cudaGetSymbolAddress((void**)&outw_l,g_outw_l);
    cudaGetSymbolAddress((void**)&xpw_h, g_xpw_h); cudaGetSymbolAddress((void**)&xpw_l, g_xpw_l);
    cudaGetSymbolAddress((void**)&pw_h,  g_pw_h);  cudaGetSymbolAddress((void**)&pw_l,  g_pw_l);

    const int SMEM128 = 1024 + 3 * (2 * 16384 + 2 * 128 * 128);  // 197632
    const int SMEM64  = 1024 + 3 * (2 * 16384 + 2 * 64 * 128);   // 148480
    cudaFuncSetAttribute(mma_gemm<128,0>, cudaFuncAttributeMaxDynamicSharedMemorySize, SMEM128);
    cudaFuncSetAttribute(mma_gemm<128,2>, cudaFuncAttributeMaxDynamicSharedMemorySize, SMEM128);
    cudaFuncSetAttribute(mma_gemm<128,3>, cudaFuncAttributeMaxDynamicSharedMemorySize, SMEM128);
    cudaFuncSetAttribute(mma_gemm<64,0>,  cudaFuncAttributeMaxDynamicSharedMemorySize, SMEM64);

    const int MT = MROWS / 128;  // 49

    // ---- weight packing (bf16 hi/lo split) ----
    // in_w [24][384][1536] -> [24][1536][384]
    transpose_split<<<dim3(12, 48, 24), 256>>>(in_w, inw_h, inw_l, 384, 1536, 1536, 384);
    // out_w [12][1536][384] -> [12][384][1536]
    transpose_split<<<dim3(48, 12, 12), 256>>>(out_w, outw_h, outw_l, 1536, 384, 384, 1536);
    // xproj_w [24][768][56] -> [24][64][768] rows>=56 zero
    transpose_split<<<dim3(24, 2, 24), 256>>>(xproj_w, xpw_h, xpw_l, 768, 56, 64, 768);
    // patch_w [384][768]
    split_copy<<<(DM*768 + 255)/256, 256>>>(patch_w, pw_h, pw_l, DM*768);

    // ---- patch embedding ----
    im2col_kernel<<<(MROWS * 768 + 255) / 256, 256>>>(images);
    mma_gemm<128,3><<<dim3(3, MT, 1), 256, SMEM128>>>(
        im_h, im_l, 768, 0,  pw_h, pw_l, 768, 0,
        x, DM, 0, DM,  768/64,  patch_b, pos_emb);

    for (int layer = 0; layer < DEPTH; layer++) {
        ln_kernel<<<MROWS, 128>>>(x, xn_h, xn_l,
                                  ln_g + (size_t)layer * DM, ln_b + (size_t)layer * DM);

        // xz[dir] = xn @ in_w[layer,dir]^T
        mma_gemm<128,0><<<dim3(12, MT, 2), 256, SMEM128>>>(
            xn_h, xn_l, DM, 0,
            inw_h + (size_t)layer * 2 * 2*DI * DM,
            inw_l + (size_t)layer * 2 * 2*DI * DM, DM, (long)2*DI * DM,
            xz, 2*DI, (long)MROWS * 2*DI, 2*DI,
            DM/64, nullptr, nullptr);

        conv_silu<<<(2 * MROWS * DI + 255) / 256, 256>>>(
            xz, conv_w + (size_t)layer * 2 * DI * 4, conv_b + (size_t)layer * 2 * DI,
            u_h, u_l);

        // dbc = u @ xproj_w   (split-bf16 tensor, N=56 padded to 64)
        mma_gemm<64,0><<<dim3(1, MT, 2), 256, SMEM64>>>(
            u_h, u_l, DI, (long)MROWS * DI,
            xpw_h + (size_t)layer * 2 * 64 * DI,
            xpw_l + (size_t)layer * 2 * 64 * DI, DI, (long)64 * DI,
            dbcv, DBCN, (long)MROWS * DBCN, DBCN,
            DI/64, nullptr, nullptr);

        // dt = softplus(dbc[:, :24] @ dt_w + dt_b)  (fp32 SIMT)
        sgemm_sp<<<dim3(DI / 64, MT, 2), 256>>>(
            dbcv, dt_w + (size_t)layer * 2 * DTR * DI, dtv,
            MROWS, DI, DTR, DBCN,
            (long)MROWS * DBCN, (long)DTR * DI, (long)MROWS * DI,
            dt_b + (size_t)layer * 2 * DI, (long)DI);

        scan_kernel<<<dim3(3, BATCHN, 2), 256>>>(
            dtv, u_h, u_l, dbcv, xz,
            A_log + (size_t)layer * 2 * DI * DS, Dp + (size_t)layer * 2 * DI,
            y_h, y_l);

        // x += y @ out_w[layer]  (dirs stacked K=1536)
        mma_gemm<128,2><<<dim3(3, MT, 1), 256, SMEM128>>>(
            y_h, y_l, 2*DI, 0,
            outw_h + (size_t)layer * DM * 2*DI,
            outw_l + (size_t)layer * DM * 2*DI, 2*DI, 0,
            x, DM, 0, DM,
            2*DI/64, nullptr, x);
    }

    final_head<<<BATCHN, 384>>>(x, fln_g, fln_b, hdev_w, hdev_b, hdist_w, hdist_b, out);
    (void)in_sizes; (void)n_in; (void)out_size;
}

// round 7
// speedup vs baseline: 2.2949x; 1.0688x over previous
#include <cuda_runtime.h>
#include <cuda_bf16.h>
#include <math.h>
#include <stdint.h>

#define BATCHN 32
#define LSEQ   196
#define DM     384
#define DI     768
#define DS     16
#define DTR    24
#define DBCN   56
#define DEPTH  12
#define MROWS  (BATCHN*LSEQ)   // 6272

#if defined(__CUDA_ARCH__) && (defined(__CUDA_ARCH_FEAT_SM103_ALL) || defined(__CUDA_ARCH_SPECIFIC__))
#define HAS_TC 1
#else
#define HAS_TC 0
#endif

typedef __nv_bfloat16 bf16;

// ---------------- scratch ----------------
__device__ __align__(256) float g_x  [MROWS*DM];
__device__ __align__(256) float g_xz [2*MROWS*2*DI];      // also reused as final-LN scratch
__device__ __align__(256) float g_dbc[2*MROWS*DBCN];
__device__ __align__(256) float g_dt [2*MROWS*DI];

__device__ __align__(256) bf16 g_xn_h[MROWS*DM],    g_xn_l[MROWS*DM];
__device__ __align__(256) bf16 g_im_h[MROWS*768],   g_im_l[MROWS*768];
__device__ __align__(256) bf16 g_u_h [2*MROWS*DI],  g_u_l [2*MROWS*DI];
__device__ __align__(256) bf16 g_y_h [MROWS*2*DI],  g_y_l [MROWS*2*DI];
__device__ __align__(256) bf16 g_dbch[2*MROWS*DBCN + 128], g_dbcl[2*MROWS*DBCN + 128];
__device__ __align__(256) bf16 g_inw_h [DEPTH*2*2*DI*DM], g_inw_l [DEPTH*2*2*DI*DM];
__device__ __align__(256) bf16 g_outw_h[DEPTH*DM*2*DI],   g_outw_l[DEPTH*DM*2*DI];
__device__ __align__(256) bf16 g_xpw_h [DEPTH*2*64*DI],   g_xpw_l [DEPTH*2*64*DI];
__device__ __align__(256) bf16 g_dtw_h [DEPTH*2*DI*64],   g_dtw_l [DEPTH*2*DI*64]; // [l*2+d][768][64], cols>=24 zero
__device__ __align__(256) bf16 g_pw_h  [DM*768],          g_pw_l  [DM*768];

__device__ __forceinline__ void split2(float v, bf16& h, bf16& l) {
    h = __float2bfloat16(v);
    l = __float2bfloat16(v - __bfloat162float(h));
}

#if HAS_TC
__device__ __forceinline__ uint32_t smem_u32(const void* p) {
    uint32_t a;
    asm("{ .reg .u64 t; cvta.to.shared.u64 t, %1; cvt.u32.u64 %0, t; }" : "=r"(a) : "l"(p));
    return a;
}
__device__ __forceinline__ uint32_t elect_one() {
    uint32_t p;
    asm volatile("{ .reg .pred p; elect.sync _|p, 0xFFFFFFFF; selp.b32 %0,1,0,p; }" : "=r"(p));
    return p;
}
#define SWZ(o) ((o) ^ (((o) >> 3) & 0x70))

static __device__ __forceinline__ uint64_t make_desc(uint32_t addr) {
    const uint64_t base =
        (uint64_t(2) << 61) | (uint64_t(1) << 46) | (uint64_t(64) << 32) | (uint64_t(1) << 16);
    return base | ((uint64_t)(addr >> 4) & 0x3FFF);
}

#define MBAR_INIT(a, c) \
    asm volatile("mbarrier.init.shared.b64 [%0], %1;" :: "r"(a), "r"(c) : "memory")
#define MBAR_INVAL(a) \
    asm volatile("mbarrier.inval.shared.b64 [%0];" :: "r"(a) : "memory")
#define MBAR_WAIT(a, ph) do {                                            \
    uint32_t _m = (a); uint32_t _p = (ph); uint32_t _d;                  \
    asm volatile("{ .reg .pred p; mbarrier.try_wait.parity.acquire.cta.shared::cta.b64 p,[%1],%2; selp.b32 %0,1,0,p; }" \
        : "=r"(_d) : "r"(_m), "r"(_p) : "memory");                       \
    if (!_d) {                                                           \
        asm volatile("{ .reg .pred P1; W%=: mbarrier.try_wait.parity.acquire.cta.shared::cta.b64 P1,[%0],%1,0x989680; @P1 bra.uni D%=; bra.uni W%=; D%=: }" \
            :: "r"(_m), "r"(_p) : "memory");                             \
    } } while (0)

#define CP_ASYNC16(dst, src) \
    asm volatile("cp.async.cg.shared.global [%0], [%1], 16;" :: "r"(dst), "l"(src) : "memory")
#define CP_COMMIT() asm volatile("cp.async.commit_group;" ::: "memory")
#define CP_WAIT1()  asm volatile("cp.async.wait_group 1;" ::: "memory")

__device__ __forceinline__ void tc_alloc(uint32_t smem_dst, uint32_t ncols) {
    asm volatile("tcgen05.alloc.cta_group::1.sync.aligned.shared::cta.b32 [%0], %1;"
                 :: "r"(smem_dst), "r"(ncols) : "memory");
}
__device__ __forceinline__ void tc_relinq() {
    asm volatile("tcgen05.relinquish_alloc_permit.cta_group::1.sync.aligned;");
}
__device__ __forceinline__ void tc_dealloc(uint32_t tmem, uint32_t ncols) {
    asm volatile("tcgen05.dealloc.cta_group::1.sync.aligned.b32 %0, %1;" :: "r"(tmem), "r"(ncols));
}
__device__ __forceinline__ void tc_commit(uint32_t mbar) {
    asm volatile("tcgen05.commit.cta_group::1.mbarrier::arrive::one.shared::cluster.b64 [%0];"
                 :: "r"(mbar) : "memory");
}
__device__ __forceinline__ void mma_bf16(uint32_t d, uint64_t ad, uint64_t bd, uint32_t idesc, bool acc) {
    uint32_t en = acc ? 1u : 0u, z = 0u;
    asm volatile(
        "{ .reg .pred p; setp.ne.u32 p, %5, 0;"
        " tcgen05.mma.cta_group::1.kind::f16 [%0], %1, %2, %3, {%4,%4,%4,%4}, p; }"
        :: "r"(d), "l"(ad), "l"(bd), "r"(idesc), "r"(z), "r"(en) : "memory");
}
#define TC_LD_X32(r, a)                                                     \
    asm volatile("tcgen05.ld.sync.aligned.32x32b.x32.b32 "                  \
        "{%0,%1,%2,%3,%4,%5,%6,%7,%8,%9,%10,%11,%12,%13,%14,%15,"           \
        "%16,%17,%18,%19,%20,%21,%22,%23,%24,%25,%26,%27,%28,%29,%30,%31}, [%32];" \
        : "=r"((r)[0]),"=r"((r)[1]),"=r"((r)[2]),"=r"((r)[3]),"=r"((r)[4]),"=r"((r)[5]),"=r"((r)[6]),"=r"((r)[7]), \
          "=r"((r)[8]),"=r"((r)[9]),"=r"((r)[10]),"=r"((r)[11]),"=r"((r)[12]),"=r"((r)[13]),"=r"((r)[14]),"=r"((r)[15]), \
          "=r"((r)[16]),"=r"((r)[17]),"=r"((r)[18]),"=r"((r)[19]),"=r"((r)[20]),"=r"((r)[21]),"=r"((r)[22]),"=r"((r)[23]), \
          "=r"((r)[24]),"=r"((r)[25]),"=r"((r)[26]),"=r"((r)[27]),"=r"((r)[28]),"=r"((r)[29]),"=r"((r)[30]),"=r"((r)[31]) \
        : "r"(a))
#define TC_WAIT_LD() asm volatile("tcgen05.wait::ld.sync.aligned;" ::: "memory")
#define TC_FENCE_AFTER() asm volatile("tcgen05.fence::after_thread_sync;" ::: "memory")
#endif  // HAS_TC

__device__ __forceinline__ float softplusf(float v) {
    return (v > 0.f) ? v + log1pf(__expf(-v)) : log1pf(__expf(v));
}

// =====================================================================
// bf16 split-precision tcgen05 GEMM, 3-stage cp.async ring, 256 threads.
// C = (Ah+Al)[M,K] @ ((Bh+Bl)[N,K])^T  ≈ Ah·Bh + Al·Bh + Ah·Bl (fp32 acc)
// K-step = 64 elements. S = K/64 (any S>=1).
// EPI: 0 plain, 1 softplus(v+bias), 2 v+res, 3 v+bias+res[(m%L)*ldc+col]
// SPLITOUT: additionally write bf16 hi/lo split of result.
// =====================================================================
template<int NT, int EPI, bool SPLITOUT>
__global__ void __launch_bounds__(256, 1) mma_gemm(
    const bf16* __restrict__ Ah, const bf16* __restrict__ Al, int lda, long sA,
    const bf16* __restrict__ Bh, const bf16* __restrict__ Bl, int ldb, long sB,
    float* __restrict__ C, int ldc, long sC, int Ncols,
    int S,
    const float* __restrict__ bias, long sBias,
    const float* __restrict__ res,
    bf16* __restrict__ Ch, bf16* __restrict__ Cl)
{
    const int tid = threadIdx.x;
    const int m0 = blockIdx.y * 128, n0 = blockIdx.x * NT;
    Ah += (size_t)blockIdx.z * sA;  Al += (size_t)blockIdx.z * sA;
    Bh += (size_t)blockIdx.z * sB;  Bl += (size_t)blockIdx.z * sB;
    C  += (size_t)blockIdx.z * sC;
    if (bias) bias += (size_t)blockIdx.z * sBias;
    if (SPLITOUT) { Ch += (size_t)blockIdx.z * sC; Cl += (size_t)blockIdx.z * sC; }

#if HAS_TC
    extern __shared__ char smem[];
    const uint32_t sb = smem_u32(smem);
    const int wid = tid >> 5, lane = tid & 31;
    constexpr int ABYTES = 128 * 128;
    constexpr int BBYTES = NT * 128;
    constexpr int STAGE  = 2 * ABYTES + 2 * BBYTES;

    if (tid == 0) {
#pragma unroll
        for (int i = 0; i < 3; i++) MBAR_INIT(sb + 8 + i * 8, 1);
    }
    if (wid == 0) { tc_alloc(sb, NT); tc_relinq(); }
    __syncthreads();
    uint32_t tmem;
    asm volatile("ld.shared.b32 %0, [%1];" : "=r"(tmem) : "r"(sb));

    const uint32_t idesc = 0x10u | (1u << 7) | (1u << 10)
                         | ((uint32_t)(NT / 8) << 17) | (8u << 24);

    auto stage_load = [&](int r, int step) {
        const int k0 = step << 6;
        const uint32_t ah = sb + 1024 + r * STAGE;
        const uint32_t al = ah + ABYTES;
        const uint32_t bh = al + ABYTES;
        const uint32_t bl = bh + BBYTES;
#pragma unroll
        for (int i = 0; i < 4; i++) {
            int c = i * 256 + tid; int row = c >> 3, q = c & 7;
            uint32_t so = SWZ(row * 128 + q * 16);
            size_t go = (size_t)(m0 + row) * lda + k0 + q * 8;
            CP_ASYNC16(ah + so, Ah + go);
            CP_ASYNC16(al + so, Al + go);
        }
#pragma unroll
        for (int i = 0; i < NT / 32; i++) {
            int c = i * 256 + tid; int row = c >> 3, q = c & 7;
            uint32_t so = SWZ(row * 128 + q * 16);
            size_t go = (size_t)(n0 + row) * ldb + k0 + q * 8;
            CP_ASYNC16(bh + so, Bh + go);
            CP_ASYNC16(bl + so, Bl + go);
        }
    };

#pragma unroll
    for (int p = 0; p < 3; p++) { if (p < S) stage_load(p, p); CP_COMMIT(); }

    int ph[3] = {0, 0, 0};
    for (int s = 0; s < S; s++) {
        CP_WAIT1();
        asm volatile("fence.proxy.async.shared::cta;" ::: "memory");
        __syncthreads();
        if (wid == 0 && elect_one()) {
            const int st = s % 3;
            const uint32_t ah = sb + 1024 + st * STAGE;
            uint64_t adh = make_desc(ah);
            uint64_t adl = make_desc(ah + ABYTES);
            uint64_t bdh = make_desc(ah + 2 * ABYTES);
            uint64_t bdl = make_desc(ah + 2 * ABYTES + BBYTES);
#pragma unroll
            for (int sl = 0; sl < 4; sl++)
                mma_bf16(tmem, adh + sl * 2, bdh + sl * 2, idesc, (s > 0) || (sl > 0));
#pragma unroll
            for (int sl = 0; sl < 4; sl++)
                mma_bf16(tmem, adl + sl * 2, bdh + sl * 2, idesc, true);
#pragma unroll
            for (int sl = 0; sl < 4; sl++)
                mma_bf16(tmem, adh + sl * 2, bdl + sl * 2, idesc, true);
            tc_commit(sb + 8 + st * 8);
        }
        if (s >= 1 && s + 2 < S) {
            const int r = (s + 2) % 3;
            MBAR_WAIT(sb + 8 + r * 8, ph[r]); ph[r] ^= 1;
            stage_load(r, s + 2);
        }
        CP_COMMIT();
    }
    MBAR_WAIT(sb + 8 + ((S - 1) % 3) * 8, ph[(S - 1) % 3]);
    TC_FENCE_AFTER();

    const int subp = wid & 3, half = wid >> 2;
#pragma unroll
    for (int ch = 0; ch < NT / 64; ch++) {
        const int chunk = half * (NT / 64) + ch;
        uint32_t r[32];
        TC_LD_X32(r, tmem + chunk * 32);
        TC_WAIT_LD();
        const int row = m0 + subp * 32 + lane;
        const int col0 = n0 + chunk * 32;
        float* cp = C + (size_t)row * ldc + col0;
        float vals[32];
#pragma unroll
        for (int j = 0; j < 32; j++) {
            float v = __uint_as_float(r[j]);
            const int col = col0 + j;
            if (EPI == 1) v = softplusf(v + bias[col]);
            if (EPI == 2) v += res[(size_t)row * ldc + col];
            if (EPI == 3) v += bias[col] + res[(size_t)(row % LSEQ) * ldc + col];
            vals[j] = v;
        }
        if (col0 + 31 < Ncols) {
#pragma unroll
            for (int g = 0; g < 8; g++)
                *(float4*)(cp + g * 4) =
                    make_float4(vals[4*g], vals[4*g+1], vals[4*g+2], vals[4*g+3]);
            if (SPLITOUT) {
#pragma unroll
                for (int j = 0; j < 32; j++) {
                    bf16 hh, ll; split2(vals[j], hh, ll);
                    Ch[(size_t)row * ldc + col0 + j] = hh;
                    Cl[(size_t)row * ldc + col0 + j] = ll;
                }
            }
        } else {
#pragma unroll
            for (int j = 0; j < 32; j++)
                if (col0 + j < Ncols) {
                    cp[j] = vals[j];
                    if (SPLITOUT) {
                        bf16 hh, ll; split2(vals[j], hh, ll);
                        Ch[(size_t)row * ldc + col0 + j] = hh;
                        Cl[(size_t)row * ldc + col0 + j] = ll;
                    }
                }
        }
    }
    __syncthreads();
    if (tid == 0) {
#pragma unroll
        for (int i = 0; i < 3; i++) MBAR_INVAL(sb + 8 + i * 8);
    }
    if (wid == 0) tc_dealloc(tmem, NT);
#else
    if (tid >= 128) return;
    const int row = m0 + tid;
    const int K = S * 64;
    for (int n = 0; n < NT; n++) {
        const int col = n0 + n;
        if (col >= Ncols) break;
        float acc = 0.f;
        for (int k = 0; k < K; k++) {
            float a = __bfloat162float(Ah[(size_t)row * lda + k]) +
                      __bfloat162float(Al[(size_t)row * lda + k]);
            float b = __bfloat162float(Bh[(size_t)col * ldb + k]) +
                      __bfloat162float(Bl[(size_t)col * ldb + k]);
            acc = fmaf(a, b, acc);
        }
        float v = acc;
        if (EPI == 1) v = softplusf(v + bias[col]);
        if (EPI == 2) v += res[(size_t)row * ldc + col];
        if (EPI == 3) v += bias[col] + res[(size_t)(row % LSEQ) * ldc + col];
        C[(size_t)row * ldc + col] = v;
        if (SPLITOUT) {
            bf16 hh, ll; split2(v, hh, ll);
            Ch[(size_t)row * ldc + col] = hh;
            Cl[(size_t)row * ldc + col] = ll;
        }
    }
#endif
}

// ---- transpose + zero-pad + bf16-split ----
__global__ void __launch_bounds__(256) transpose_split(
    const float* __restrict__ in, bf16* __restrict__ oh, bf16* __restrict__ ol,
    int R, int C, int OR_, int OC)
{
    __shared__ float t[32][33];
    const int z = blockIdx.z;
    in += (size_t)z * R * C;
    oh += (size_t)z * OR_ * OC;
    ol += (size_t)z * OR_ * OC;
    const int j0 = blockIdx.x * 32;
    const int i0 = blockIdx.y * 32;
    const int tx = threadIdx.x & 31, ty = threadIdx.x >> 5;
#pragma unroll
    for (int k = 0; k < 4; k++) {
        int rin = j0 + ty + k * 8, cin = i0 + tx;
        t[ty + k * 8][tx] = (rin < R && cin < C) ? in[(size_t)rin * C + cin] : 0.f;
    }
    __syncthreads();
#pragma unroll
    for (int k = 0; k < 4; k++) {
        int orow = i0 + ty + k * 8, ocol = j0 + tx;
        if (orow < OR_ && ocol < OC) {
            bf16 h, l; split2(t[tx][ty + k * 8], h, l);
            oh[(size_t)orow * OC + ocol] = h;
            ol[(size_t)orow * OC + ocol] = l;
        }
    }
}

__global__ void split_copy(const float* __restrict__ in,
                           bf16* __restrict__ oh, bf16* __restrict__ ol, int n)
{
    int i = blockIdx.x * blockDim.x + threadIdx.x;
    if (i < n) { bf16 h, l; split2(in[i], h, l); oh[i] = h; ol[i] = l; }
}

// ---------------- LayerNorm -> bf16 hi/lo ----------------
__global__ void __launch_bounds__(128) ln_kernel(
    const float* __restrict__ x, bf16* __restrict__ yh, bf16* __restrict__ yl,
    const float* __restrict__ g, const float* __restrict__ b)
{
    const int row = blockIdx.x;
    const int tid = threadIdx.x;
    const float* xr = x + (size_t)row * DM;
    float v0 = xr[tid], v1 = xr[tid + 128], v2 = xr[tid + 256];
    __shared__ float sh[4];
    float s = v0 + v1 + v2;
#pragma unroll
    for (int o = 16; o > 0; o >>= 1) s += __shfl_xor_sync(0xffffffffu, s, o);
    if ((tid & 31) == 0) sh[tid >> 5] = s;
    __syncthreads();
    float mu = (sh[0] + sh[1] + sh[2] + sh[3]) * (1.f / DM);
    float d0 = v0 - mu, d1 = v1 - mu, d2 = v2 - mu;
    float q = d0*d0 + d1*d1 + d2*d2;
    __syncthreads();
#pragma unroll
    for (int o = 16; o > 0; o >>= 1) q += __shfl_xor_sync(0xffffffffu, q, o);
    if ((tid & 31) == 0) sh[tid >> 5] = q;
    __syncthreads();
    float var = (sh[0] + sh[1] + sh[2] + sh[3]) * (1.f / DM);
    float rs = rsqrtf(var + 1e-5f);
    bf16 h, l;
    size_t base = (size_t)row * DM;
    split2(d0 * rs * g[tid]       + b[tid],       h, l); yh[base + tid]       = h; yl[base + tid]       = l;
    split2(d1 * rs * g[tid + 128] + b[tid + 128], h, l); yh[base + tid + 128] = h; yl[base + tid + 128] = l;
    split2(d2 * rs * g[tid + 256] + b[tid + 256], h, l); yh[base + tid + 256] = h; yl[base + tid + 256] = l;
}

// ---------------- final LayerNorm -> fp32 ----------------
__global__ void __launch_bounds__(128) ln_f32(
    const float* __restrict__ x, float* __restrict__ y,
    const float* __restrict__ g, const float* __restrict__ b)
{
    const int row = blockIdx.x;
    const int tid = threadIdx.x;
    const float* xr = x + (size_t)row * DM;
    float v0 = xr[tid], v1 = xr[tid + 128], v2 = xr[tid + 256];
    __shared__ float sh[4];
    float s = v0 + v1 + v2;
#pragma unroll
    for (int o = 16; o > 0; o >>= 1) s += __shfl_xor_sync(0xffffffffu, s, o);
    if ((tid & 31) == 0) sh[tid >> 5] = s;
    __syncthreads();
    float mu = (sh[0] + sh[1] + sh[2] + sh[3]) * (1.f / DM);
    float d0 = v0 - mu, d1 = v1 - mu, d2 = v2 - mu;
    float q = d0*d0 + d1*d1 + d2*d2;
    __syncthreads();
#pragma unroll
    for (int o = 16; o > 0; o >>= 1) q += __shfl_xor_sync(0xffffffffu, q, o);
    if ((tid & 31) == 0) sh[tid >> 5] = q;
    __syncthreads();
    float var = (sh[0] + sh[1] + sh[2] + sh[3]) * (1.f / DM);
    float rs = rsqrtf(var + 1e-5f);
    float* yr = y + (size_t)row * DM;
    yr[tid]       = d0 * rs * g[tid]       + b[tid];
    yr[tid + 128] = d1 * rs * g[tid + 128] + b[tid + 128];
    yr[tid + 256] = d2 * rs * g[tid + 256] + b[tid + 256];
}

// ---------------- conv1d + SiLU, 4 channels/thread ----------------
__global__ void conv_silu(const float* __restrict__ xz, const float* __restrict__ w,
                          const float* __restrict__ bias,
                          bf16* __restrict__ uh, bf16* __restrict__ ul)
{
    const int CQ = DI / 4;
    int idx = blockIdx.x * blockDim.x + threadIdx.x;
    if (idx >= 2 * MROWS * CQ) return;
    int q   = idx % CQ;  int c4 = q * 4;
    int m   = (idx / CQ) % MROWS;
    int dir = idx / (CQ * MROWS);
    int l = m % LSEQ, mbase = m - l;
    const float* xzd = xz + (size_t)dir * MROWS * 2 * DI;
    const float* wp = w + (size_t)dir * DI * 4 + c4 * 4;
    float4 w0 = *(const float4*)(wp);
    float4 w1 = *(const float4*)(wp + 4);
    float4 w2 = *(const float4*)(wp + 8);
    float4 w3 = *(const float4*)(wp + 12);
    float4 bv = *(const float4*)(bias + dir * DI + c4);
    float a0 = bv.x, a1 = bv.y, a2 = bv.z, a3 = bv.w;
    const float wk0[4] = {w0.x, w0.y, w0.z, w0.w};
    const float wk1[4] = {w1.x, w1.y, w1.z, w1.w};
    const float wk2[4] = {w2.x, w2.y, w2.z, w2.w};
    const float wk3[4] = {w3.x, w3.y, w3.z, w3.w};
#pragma unroll
    for (int k = 0; k < 4; k++) {
        int ls = dir ? (l + 3 - k) : (l - 3 + k);
        if (ls >= 0 && ls < LSEQ) {
            float4 xv = *(const float4*)(xzd + (size_t)(mbase + ls) * 2 * DI + c4);
            a0 = fmaf(wk0[k], xv.x, a0);
            a1 = fmaf(wk1[k], xv.y, a1);
            a2 = fmaf(wk2[k], xv.z, a2);
            a3 = fmaf(wk3[k], xv.w, a3);
        }
    }
    float u0 = a0 / (1.f + __expf(-a0));
    float u1 = a1 / (1.f + __expf(-a1));
    float u2 = a2 / (1.f + __expf(-a2));
    float u3 = a3 / (1.f + __expf(-a3));
    size_t o = (size_t)dir * MROWS * DI + (size_t)m * DI + c4;
    bf16 h0,l0,h1,l1,h2,l2,h3,l3;
    split2(u0,h0,l0); split2(u1,h1,l1); split2(u2,h2,l2); split2(u3,h3,l3);
    __nv_bfloat162* uhp = (__nv_bfloat162*)(uh + o);
    __nv_bfloat162* ulp = (__nv_bfloat162*)(ul + o);
    __nv_bfloat162 t;
    t.x = h0; t.y = h1; uhp[0] = t;
    t.x = h2; t.y = h3; uhp[1] = t;
    t.x = l0; t.y = l1; ulp[0] = t;
    t.x = l2; t.y = l3; ulp[1] = t;
}

// ---------------- selective scan (prefetched, exp-power fast path) ----------------
__global__ void __launch_bounds__(128) scan_kernel(
    const float* __restrict__ dt,
    const bf16* __restrict__ uh, const bf16* __restrict__ ul,
    const float* __restrict__ dbc, const float* __restrict__ xz,
    const float* __restrict__ A_log, const float* __restrict__ Dp,
    bf16* __restrict__ yh, bf16* __restrict__ yl)
{
    const int c   = blockIdx.x * 128 + threadIdx.x;
    const int b   = blockIdx.y;
    const int dir = blockIdx.z;

    __shared__ float Bsh[LSEQ][DS];
    __shared__ float Csh[LSEQ][DS];
    const float* dbcb = dbc + ((size_t)dir * MROWS + (size_t)b * LSEQ) * DBCN;
    for (int i = threadIdx.x; i < LSEQ * 2 * DS; i += 128) {
        int l = i >> 5, j = i & 31;
        float v = dbcb[(size_t)l * DBCN + DTR + j];
        if (j < DS) Bsh[l][j] = v; else Csh[l][j - DS] = v;
    }
    __syncthreads();

    float a[DS];
    const float* ap = A_log + ((size_t)dir * DI + c) * DS;
#pragma unroll
    for (int n = 0; n < DS; n++) a[n] = -__expf(ap[n]);
    const float a0 = a[0];
    bool fast = true;
#pragma unroll
    for (int n = 1; n < DS; n++)
        fast = fast && (fabsf(a[n] - a0 * (float)(n + 1)) <= 1e-4f * fabsf(a[n]));
    const float dp = Dp[dir * DI + c];

    float h[DS];
#pragma unroll
    for (int n = 0; n < DS; n++) h[n] = 0.f;

    const size_t ubase = ((size_t)dir * MROWS + (size_t)b * LSEQ) * DI + c;
    const float* dtb = dt + ubase;
    const float* zb  = xz + ((size_t)dir * MROWS + (size_t)b * LSEQ) * 2 * DI + DI + c;
    const size_t ybase = ((size_t)b * LSEQ) * 2 * DI + (size_t)dir * DI + c;

    // prefetch t=0
    int l = dir ? (LSEQ - 1) : 0;
    float dt_n = dtb[(size_t)l * DI];
    float uh_n = __bfloat162float(uh[ubase + (size_t)l * DI]);
    float ul_n = __bfloat162float(ul[ubase + (size_t)l * DI]);
    float z_n  = zb[(size_t)l * 2 * DI];

    for (int t = 0; t < LSEQ; t++) {
        const int lc = l;
        const float dtv = dt_n;
        const float uv  = uh_n + ul_n;
        const float zv  = z_n;
        if (t + 1 < LSEQ) {
            l = dir ? (LSEQ - 2 - t) : (t + 1);
            dt_n = dtb[(size_t)l * DI];
            uh_n = __bfloat162float(uh[ubase + (size_t)l * DI]);
            ul_n = __bfloat162float(ul[ubase + (size_t)l * DI]);
            z_n  = zb[(size_t)l * 2 * DI];
        }
        const float du = dtv * uv;
        float acc = 0.f;
        if (fast) {
            const float e1 = __expf(dtv * a0);
            float p = 1.f;
#pragma unroll
            for (int n = 0; n < DS; n++) {
                p *= e1;
                h[n] = p * h[n] + du * Bsh[lc][n];
                acc = fmaf(h[n], Csh[lc][n], acc);
            }
        } else {
#pragma unroll
            for (int n = 0; n < DS; n++) {
                h[n] = __expf(dtv * a[n]) * h[n] + du * Bsh[lc][n];
                acc = fmaf(h[n], Csh[lc][n], acc);
            }
        }
        const float yv = acc + dp * uv;
        const float og = yv * (zv / (1.f + __expf(-zv)));
        bf16 hh, ll; split2(og, hh, ll);
        yh[ybase + (size_t)lc * 2 * DI] = hh;
        yl[ybase + (size_t)lc * 2 * DI] = ll;
    }
}

// ---------------- pool + heads (after ln_f32) ----------------
__global__ void __launch_bounds__(384) pool_head(
    const float* __restrict__ fln,
    const float* __restrict__ wdev, const float* __restrict__ bdev,
    const float* __restrict__ wdist, const float* __restrict__ bdist,
    float* __restrict__ out)
{
    const int b = blockIdx.x;
    const int tid = threadIdx.x;
    __shared__ float pooled_s[DM];
    float s = 0.f;
    for (int l = 0; l < LSEQ; l++)
        s += fln[((size_t)b * LSEQ + l) * DM + tid];
    pooled_s[tid] = s * (1.f / LSEQ);
    __syncthreads();
    if (tid < 7) {
        float acc = bdev[tid];
        for (int d = 0; d < DM; d++) acc += pooled_s[d] * wdev[d * 7 + tid];
        out[b * 7 + tid] = acc;
    } else if (tid < 11) {
        int j = tid - 7;
        float acc = bdist[j];
        for (int d = 0; d < DM; d++) acc += pooled_s[d] * wdist[d * 4 + j];
        out[BATCHN * 7 + b * 4 + j] = acc;
    }
}

// ---------------- im2col -> bf16 hi/lo ----------------
__global__ void im2col_kernel(const float* __restrict__ img)
{
    int idx = blockIdx.x * blockDim.x + threadIdx.x;
    if (idx >= MROWS * 768) return;
    int k = idx % 768;
    int m = idx / 768;
    int b = m / LSEQ, l = m % LSEQ;
    int ph = l / 14, pw = l % 14;
    int ch  = k >> 8;
    int r   = (k >> 4) & 15;
    int col = k & 15;
    float v = img[(((size_t)b * 3 + ch) * 224 + ph * 16 + r) * 224 + pw * 16 + col];
    bf16 h, lo; split2(v, h, lo);
    g_im_h[idx] = h; g_im_l[idx] = lo;
}

// ---------------- launcher ----------------
extern "C" void kernel_launch(void* const* d_in, const int* in_sizes, int n_in,
                              void* d_out, int out_size)
{
    const float* images  = (const float*)d_in[0];
    const float* patch_w = (const float*)d_in[1];
    const float* patch_b = (const float*)d_in[2];
    const float* pos_emb = (const float*)d_in[3];
    const float* ln_g    = (const float*)d_in[4];
    const float* ln_b    = (const float*)d_in[5];
    const float* in_w    = (const float*)d_in[6];
    const float* conv_w  = (const float*)d_in[7];
    const float* conv_b  = (const float*)d_in[8];
    const float* xproj_w = (const float*)d_in[9];
    const float* dt_w    = (const float*)d_in[10];
    const float* dt_b    = (const float*)d_in[11];
    const float* A_log   = (const float*)d_in[12];
    const float* Dp      = (const float*)d_in[13];
    const float* out_w   = (const float*)d_in[14];
    const float* fln_g   = (const float*)d_in[15];
    const float* fln_b   = (const float*)d_in[16];
    const float* hdev_w  = (const float*)d_in[17];
    const float* hdev_b  = (const float*)d_in[18];
    const float* hdist_w = (const float*)d_in[19];
    const float* hdist_b = (const float*)d_in[20];
    float* out = (float*)d_out;

    float *x, *xz, *dbcv, *dtv;
    bf16 *xn_h, *xn_l, *im_h, *im_l, *u_h, *u_l, *y_h, *y_l, *dbch, *dbcl;
    bf16 *inw_h, *inw_l, *outw_h, *outw_l, *xpw_h, *xpw_l, *dtw_h, *dtw_l, *pw_h, *pw_l;
    cudaGetSymbolAddress((void**)&x,     g_x);
    cudaGetSymbolAddress((void**)&xz,    g_xz);
    cudaGetSymbolAddress((void**)&dbcv,  g_dbc);
    cudaGetSymbolAddress((void**)&dtv,   g_dt);
    cudaGetSymbolAddress((void**)&xn_h,  g_xn_h);  cudaGetSymbolAddress((void**)&xn_l,  g_xn_l);
    cudaGetSymbolAddress((void**)&im_h,  g_im_h);  cudaGetSymbolAddress((void**)&im_l,  g_im_l);
    cudaGetSymbolAddress((void**)&u_h,   g_u_h);   cudaGetSymbolAddress((void**)&u_l,   g_u_l);
    cudaGetSymbolAddress((void**)&y_h,   g_y_h);   cudaGetSymbolAddress((void**)&y_l,   g_y_l);
    cudaGetSymbolAddress((void**)&dbch,  g_dbch);  cudaGetSymbolAddress((void**)&dbcl,  g_dbcl);
    cudaGetSymbolAddress((void**)&inw_h, g_inw_h); cudaGetSymbolAddress((void**)&inw_l, g_inw_l);
    cudaGetSymbolAddress((void**)&outw_h,g_outw_h);cudaGetSymbolAddress((void**)&outw_l,g_outw_l);
    cudaGetSymbolAddress((void**)&xpw_h, g_xpw_h); cudaGetSymbolAddress((void**)&xpw_l, g_xpw_l);
    cudaGetSymbolAddress((void**)&dtw_h, g_dtw_h); cudaGetSymbolAddress((void**)&dtw_l, g_dtw_l);
    cudaGetSymbolAddress((void**)&pw_h,  g_pw_h);  cudaGetSymbolAddress((void**)&pw_l,  g_pw_l);

    const int SMEM128 = 1024 + 3 * (2 * 16384 + 2 * 128 * 128);  // 197632
    const int SMEM64  = 1024 + 3 * (2 * 16384 + 2 * 64 * 128);   // 148480
    cudaFuncSetAttribute(mma_gemm<128,0,false>, cudaFuncAttributeMaxDynamicSharedMemorySize, SMEM128);
    cudaFuncSetAttribute(mma_gemm<128,1,false>, cudaFuncAttributeMaxDynamicSharedMemorySize, SMEM128);
    cudaFuncSetAttribute(mma_gemm<128,2,false>, cudaFuncAttributeMaxDynamicSharedMemorySize, SMEM128);
    cudaFuncSetAttribute(mma_gemm<128,3,false>, cudaFuncAttributeMaxDynamicSharedMemorySize, SMEM128);
    cudaFuncSetAttribute(mma_gemm<64,0,true>,   cudaFuncAttributeMaxDynamicSharedMemorySize, SMEM64);

    const int MT = MROWS / 128;  // 49

    // ---- weight packing (bf16 hi/lo split, zero-padded) ----
    transpose_split<<<dim3(12, 48, 24), 256>>>(in_w, inw_h, inw_l, 384, 1536, 1536, 384);
    transpose_split<<<dim3(48, 12, 12), 256>>>(out_w, outw_h, outw_l, 1536, 384, 384, 1536);
    transpose_split<<<dim3(24, 2, 24), 256>>>(xproj_w, xpw_h, xpw_l, 768, 56, 64, 768);
    transpose_split<<<dim3(2, 24, 24), 256>>>(dt_w, dtw_h, dtw_l, 24, 768, 768, 64);
    split_copy<<<(DM*768 + 255)/256, 256>>>(patch_w, pw_h, pw_l, DM*768);

    // ---- patch embedding ----
    im2col_kernel<<<(MROWS * 768 + 255) / 256, 256>>>(images);
    mma_gemm<128,3,false><<<dim3(3, MT, 1), 256, SMEM128>>>(
        im_h, im_l, 768, 0,  pw_h, pw_l, 768, 0,
        x, DM, 0, DM,  768/64,  patch_b, 0, pos_emb, nullptr, nullptr);

    for (int layer = 0; layer < DEPTH; layer++) {
        ln_kernel<<<MROWS, 128>>>(x, xn_h, xn_l,
                                  ln_g + (size_t)layer * DM, ln_b + (size_t)layer * DM);

        // xz[dir] = xn @ in_w^T
        mma_gemm<128,0,false><<<dim3(12, MT, 2), 256, SMEM128>>>(
            xn_h, xn_l, DM, 0,
            inw_h + (size_t)layer * 2 * 2*DI * DM,
            inw_l + (size_t)layer * 2 * 2*DI * DM, DM, (long)2*DI * DM,
            xz, 2*DI, (long)MROWS * 2*DI, 2*DI,
            DM/64, nullptr, 0, nullptr, nullptr, nullptr);

        conv_silu<<<(2 * MROWS * (DI/4) + 255) / 256, 256>>>(
            xz, conv_w + (size_t)layer * 2 * DI * 4, conv_b + (size_t)layer * 2 * DI,
            u_h, u_l);

        // dbc = u @ xproj_w  (fp32 + split outputs)
        mma_gemm<64,0,true><<<dim3(1, MT, 2), 256, SMEM64>>>(
            u_h, u_l, DI, (long)MROWS * DI,
            xpw_h + (size_t)layer * 2 * 64 * DI,
            xpw_l + (size_t)layer * 2 * 64 * DI, DI, (long)64 * DI,
            dbcv, DBCN, (long)MROWS * DBCN, DBCN,
            DI/64, nullptr, 0, nullptr, dbch, dbcl);

        // dt = softplus(dbc[:, :24] @ dt_w + dt_b)  (tensor, K padded 24->64)
        mma_gemm<128,1,false><<<dim3(6, MT, 2), 256, SMEM128>>>(
            dbch, dbcl, DBCN, (long)MROWS * DBCN,
            dtw_h + (size_t)layer * 2 * DI * 64,
            dtw_l + (size_t)layer * 2 * DI * 64, 64, (long)DI * 64,
            dtv, DI, (long)MROWS * DI, DI,
            1, dt_b + (size_t)layer * 2 * DI, (long)DI, nullptr, nullptr, nullptr);

        scan_kernel<<<dim3(6, BATCHN, 2), 128>>>(
            dtv, u_h, u_l, dbcv, xz,
            A_log + (size_t)layer * 2 * DI * DS, Dp + (size_t)layer * 2 * DI,
            y_h, y_l);

        // x += y @ out_w  (dirs stacked K=1536)
        mma_gemm<128,2,false><<<dim3(3, MT, 1), 256, SMEM128>>>(
            y_h, y_l, 2*DI, 0,
            outw_h + (size_t)layer * DM * 2*DI,
            outw_l + (size_t)layer * DM * 2*DI, 2*DI, 0,
            x, DM, 0, DM,
            2*DI/64, nullptr, 0, x, nullptr, nullptr);
    }

    // final LN (fp32, into xz scratch) + pool + heads
    ln_f32<<<MROWS, 128>>>(x, xz, fln_g, fln_b);
    pool_head<<<BATCHN, 384>>>(xz, hdev_w, hdev_b, hdist_w, hdist_b, out);
    (void)in_sizes; (void)n_in; (void)out_size;
}